// round 10
// baseline (speedup 1.0000x reference)
#include <cuda_runtime.h>
#include <cuda_fp16.h>
#include <cstdint>

// Problem constants (B=64, H=W=56, C=256, heads=8, hd=32, ws=7, shift=3)
#define IMG 56
#define CH 256
#define NHEAD 8
#define HD 32
#define WS 7
#define NWIN 64
#define NTOK 49
#define BATCH 64
#define M_TOTAL (BATCH * IMG * IMG)   // 200704
#define QKV_N 768
#define QSCALE 0.17677669529663687f

// Scratch
__device__ float g_qkv[(size_t)M_TOTAL * QKV_N];     // window-order [m, 768]
__device__ float g_attnout[(size_t)M_TOTAL * CH];    // window-order [m, 256]

// ---- index helper ------------------------------------------------------
__device__ __forceinline__ int gather_src_row(int m) {
    int win = m / NTOK, n = m - win * NTOK;
    int b = win >> 6, wl = win & 63;
    int hr = (wl >> 3) * WS + n / WS;
    int wr = (wl & 7) * WS + n % WS;
    int h = hr + 3; if (h >= IMG) h -= IMG;
    int w = wr + 3; if (w >= IMG) w -= IMG;
    return (b * IMG + h) * IMG + w;
}

// split a float pair into packed fp16x2 hi and lo
__device__ __forceinline__ void split_pack(float a, float b, uint32_t& hi, uint32_t& lo) {
    __half2 h = __floats2half2_rn(a, b);
    float2 hf = __half22float2(h);
    __half2 l = __floats2half2_rn(a - hf.x, b - hf.y);
    hi = *reinterpret_cast<uint32_t*>(&h);
    lo = *reinterpret_cast<uint32_t*>(&l);
}

// fp16 inputs, fp32 accumulator (double-pumped)
__device__ __forceinline__ void mma_f32(float* c,
    uint32_t a0, uint32_t a1, uint32_t a2, uint32_t a3,
    uint32_t b0, uint32_t b1) {
    asm volatile(
        "mma.sync.aligned.m16n8k16.row.col.f32.f16.f16.f32 "
        "{%0,%1,%2,%3}, {%4,%5,%6,%7}, {%8,%9}, {%0,%1,%2,%3};"
        : "+f"(c[0]), "+f"(c[1]), "+f"(c[2]), "+f"(c[3])
        : "r"(a0), "r"(a1), "r"(a2), "r"(a3), "r"(b0), "r"(b1));
}

// fp16 inputs, fp16 accumulator (single-pass candidate)
__device__ __forceinline__ void mma_f16(uint32_t* c,
    uint32_t a0, uint32_t a1, uint32_t a2, uint32_t a3,
    uint32_t b0, uint32_t b1) {
    asm volatile(
        "mma.sync.aligned.m16n8k16.row.col.f16.f16.f16.f16 "
        "{%0,%1}, {%2,%3,%4,%5}, {%6,%7}, {%0,%1};"
        : "+r"(c[0]), "+r"(c[1])
        : "r"(a0), "r"(a1), "r"(a2), "r"(a3), "r"(b0), "r"(b1));
}

__device__ __forceinline__ float2 h2f(uint32_t u) {
    __half2 h = *reinterpret_cast<__half2*>(&u);
    return __half22float2(h);
}

// ---- HMMA GEMM: 128x128 tile, 512 threads (16 warps of 32x32), BK=32 ---
#define BK 32
#define SA 40
#define T_ELEMS (128 * SA)                 // 5120 halfs per matrix
#define STG_ELEMS (4 * T_ELEMS)            // Ahi|Alo|Bhi|Blo
#define SMEM_GEMM (2 * STG_ELEMS * 2)      // 81920 bytes

template <int MODE>
__global__ void __launch_bounds__(512, 1) tc_gemm(
    const float* __restrict__ A, const float* __restrict__ W,
    const float* __restrict__ bias, float* __restrict__ out)
{
    extern __shared__ __half sm[];
    const int tid = threadIdx.x;
    const int wid = tid >> 5;
    const int lane = tid & 31;
    const int gid = lane >> 2;
    const int t4 = lane & 3;
    const int wm = wid & 3;          // 4 row groups of 32
    const int wn = wid >> 2;         // 4 col groups of 32
    const int bm = blockIdx.y * 128;
    const int bn = blockIdx.x * 128;
    const int OUT_STRIDE = (MODE == 0) ? QKV_N : CH;

    // loaders: row = tid>>2 (0..127), 8 k's
    const int arow = tid >> 2;
    const int ak = (tid & 3) * 8;
    const float* Arow = (MODE == 0)
        ? (A + (size_t)gather_src_row(bm + arow) * CH)
        : (A + (size_t)(bm + arow) * CH);
    const float* Brow = W + (size_t)(bn + arow) * CH;

    float facc[2][4][4];
    uint32_t hacc[2][4][2];
#pragma unroll
    for (int mt = 0; mt < 2; mt++)
#pragma unroll
        for (int nt = 0; nt < 4; nt++) {
#pragma unroll
            for (int r = 0; r < 4; r++) facc[mt][nt][r] = 0.f;
            hacc[mt][nt][0] = 0u; hacc[mt][nt][1] = 0u;
        }

    auto Ahi = [&](int st) { return sm + st * STG_ELEMS; };
    auto Alo = [&](int st) { return sm + st * STG_ELEMS + T_ELEMS; };
    auto Bhi = [&](int st) { return sm + st * STG_ELEMS + 2 * T_ELEMS; };
    auto Blo = [&](int st) { return sm + st * STG_ELEMS + 3 * T_ELEMS; };

    auto sts_stage = [&](int st, const float4* av, const float4* bv) {
        uint32_t h0, l0, h1, l1;
        uint32_t* ph = (uint32_t*)(Ahi(st) + arow * SA + ak);
        uint32_t* pl = (uint32_t*)(Alo(st) + arow * SA + ak);
        split_pack(av[0].x, av[0].y, h0, l0); ph[0] = h0; pl[0] = l0;
        split_pack(av[0].z, av[0].w, h1, l1); ph[1] = h1; pl[1] = l1;
        split_pack(av[1].x, av[1].y, h0, l0); ph[2] = h0; pl[2] = l0;
        split_pack(av[1].z, av[1].w, h1, l1); ph[3] = h1; pl[3] = l1;
        uint32_t* qh = (uint32_t*)(Bhi(st) + arow * SA + ak);
        uint32_t* ql = (uint32_t*)(Blo(st) + arow * SA + ak);
        split_pack(bv[0].x, bv[0].y, h0, l0); qh[0] = h0; ql[0] = l0;
        split_pack(bv[0].z, bv[0].w, h1, l1); qh[1] = h1; ql[1] = l1;
        split_pack(bv[1].x, bv[1].y, h0, l0); qh[2] = h0; ql[2] = l0;
        split_pack(bv[1].z, bv[1].w, h1, l1); qh[3] = h1; ql[3] = l1;
    };

    float4 av[2], bv[2];
    av[0] = *(const float4*)(Arow + ak);
    av[1] = *(const float4*)(Arow + ak + 4);
    bv[0] = *(const float4*)(Brow + ak);
    bv[1] = *(const float4*)(Brow + ak + 4);
    sts_stage(0, av, bv);
    __syncthreads();

    const int NSTAGE = CH / BK;   // 8
    for (int s = 0; s < NSTAGE; s++) {
        const int p = s & 1;
        if (s + 1 < NSTAGE) {
            const int k0 = (s + 1) * BK;
            av[0] = *(const float4*)(Arow + k0 + ak);
            av[1] = *(const float4*)(Arow + k0 + ak + 4);
            bv[0] = *(const float4*)(Brow + k0 + ak);
            bv[1] = *(const float4*)(Brow + k0 + ak + 4);
        }

        const __half* Ah = Ahi(p);
        const __half* Al = Alo(p);
        const __half* Bh = Bhi(p);
        const __half* Bl = Blo(p);
#pragma unroll
        for (int ksub = 0; ksub < 2; ksub++) {
            const int kk = ksub * 16 + 2 * t4;
            uint32_t ah[2][4], al[2][4];
#pragma unroll
            for (int mt = 0; mt < 2; mt++) {
                int r = wm * 32 + mt * 16 + gid;
                ah[mt][0] = *(const uint32_t*)(Ah + r * SA + kk);
                ah[mt][1] = *(const uint32_t*)(Ah + (r + 8) * SA + kk);
                ah[mt][2] = *(const uint32_t*)(Ah + r * SA + kk + 8);
                ah[mt][3] = *(const uint32_t*)(Ah + (r + 8) * SA + kk + 8);
                al[mt][0] = *(const uint32_t*)(Al + r * SA + kk);
                al[mt][1] = *(const uint32_t*)(Al + (r + 8) * SA + kk);
                al[mt][2] = *(const uint32_t*)(Al + r * SA + kk + 8);
                al[mt][3] = *(const uint32_t*)(Al + (r + 8) * SA + kk + 8);
            }
#pragma unroll
            for (int nt = 0; nt < 4; nt++) {
                int c = wn * 32 + nt * 8 + gid;
                uint32_t bh0 = *(const uint32_t*)(Bh + c * SA + kk);
                uint32_t bh1 = *(const uint32_t*)(Bh + c * SA + kk + 8);
                uint32_t bl0 = *(const uint32_t*)(Bl + c * SA + kk);
                uint32_t bl1 = *(const uint32_t*)(Bl + c * SA + kk + 8);
#pragma unroll
                for (int mt = 0; mt < 2; mt++) {
                    mma_f32(facc[mt][nt], ah[mt][0], ah[mt][1], ah[mt][2], ah[mt][3], bh0, bh1);
                    mma_f16(hacc[mt][nt], ah[mt][0], ah[mt][1], ah[mt][2], ah[mt][3], bl0, bl1);
                    mma_f16(hacc[mt][nt], al[mt][0], al[mt][1], al[mt][2], al[mt][3], bh0, bh1);
                }
            }
        }
        __syncthreads();
        if (s + 1 < NSTAGE) {
            sts_stage((s + 1) & 1, av, bv);
            __syncthreads();
        }
    }

#pragma unroll
    for (int mt = 0; mt < 2; mt++) {
        int m1 = bm + wm * 32 + mt * 16 + gid;
        int m2 = m1 + 8;
        float* d1;
        float* d2;
        if (MODE == 0) {
            d1 = out + (size_t)m1 * OUT_STRIDE;
            d2 = out + (size_t)m2 * OUT_STRIDE;
        } else {
            d1 = out + (size_t)gather_src_row(m1) * OUT_STRIDE;
            d2 = out + (size_t)gather_src_row(m2) * OUT_STRIDE;
        }
#pragma unroll
        for (int nt = 0; nt < 4; nt++) {
            int n = bn + wn * 32 + nt * 8 + 2 * t4;
            float2 bv2 = *(const float2*)(bias + n);
            float2 c0 = h2f(hacc[mt][nt][0]);
            float2 c1 = h2f(hacc[mt][nt][1]);
            float2 r1, r2;
            r1.x = facc[mt][nt][0] + c0.x + bv2.x;
            r1.y = facc[mt][nt][1] + c0.y + bv2.y;
            r2.x = facc[mt][nt][2] + c1.x + bv2.x;
            r2.y = facc[mt][nt][3] + c1.y + bv2.y;
            *(float2*)(d1 + n) = r1;
            *(float2*)(d2 + n) = r2;
        }
    }
}

// ---- HMMA window attention: one warp per (window, head) -----------------
__global__ void __launch_bounds__(32) attn_mma_kernel(
    const float* __restrict__ qkv, const float* __restrict__ table,
    float* __restrict__ out)
{
    const int blk = blockIdx.x;
    const int win = blk >> 3;
    const int head = blk & 7;
    const int lane = threadIdx.x;
    const int gid = lane >> 2;
    const int t4 = lane & 3;
    const int wl = win & 63;
    const int hbase = (wl >> 3) * WS;
    const int wbase = (wl & 7) * WS;

    __shared__ uint32_t KH[64 * 17], KL[64 * 17];
    __shared__ uint32_t VTH[32 * 33], VTL[32 * 33];
    __shared__ float TBL[169];

    for (int t = lane; t < 169; t += 32) TBL[t] = table[t * NHEAD + head];

    const float* base = qkv + (size_t)win * NTOK * QKV_N + head * HD;

    // K: cooperative coalesced load, split fp16, zero padding rows
    for (int r = lane; r < 64; r += 32) {
        bool valid = r < NTOK;
        const float* p = base + (size_t)(valid ? r : 0) * QKV_N + 256;
#pragma unroll
        for (int j = 0; j < 8; j++) {
            float4 kv = valid ? *(const float4*)(p + 4 * j) : make_float4(0, 0, 0, 0);
            uint32_t h0, l0, h1, l1;
            split_pack(kv.x, kv.y, h0, l0); split_pack(kv.z, kv.w, h1, l1);
            KH[r * 17 + 2 * j] = h0; KH[r * 17 + 2 * j + 1] = h1;
            KL[r * 17 + 2 * j] = l0; KL[r * 17 + 2 * j + 1] = l1;
        }
    }

    // V transposed directly from gmem: lane = d, coalesced per token
    const float* vbase = base + 512;
#pragma unroll 4
    for (int tp = 0; tp < 32; tp++) {
        int t0 = 2 * tp, t1 = 2 * tp + 1;
        float a = (t0 < NTOK) ? vbase[(size_t)t0 * QKV_N + lane] : 0.f;
        float b = (t1 < NTOK) ? vbase[(size_t)t1 * QKV_N + lane] : 0.f;
        uint32_t h, l; split_pack(a, b, h, l);
        VTH[lane * 33 + tp] = h; VTL[lane * 33 + tp] = l;
    }
    __syncwarp();

    float o[4][4][4];
    uint32_t ho[4][4][2];
#pragma unroll
    for (int a = 0; a < 4; a++)
#pragma unroll
        for (int b = 0; b < 4; b++) {
#pragma unroll
            for (int r = 0; r < 4; r++) o[a][b][r] = 0.f;
            ho[a][b][0] = 0u; ho[a][b][1] = 0u;
        }

#pragma unroll
    for (int mt = 0; mt < 4; mt++) {
        const int r0 = mt * 16 + gid;
        const int rc0 = min(r0, NTOK - 1);
        const int rc1 = min(r0 + 8, NTOK - 1);
        const float* q0 = base + (size_t)rc0 * QKV_N;
        const float* q1 = base + (size_t)rc1 * QKV_N;

        // Q A-fragments straight from gmem (scaled, split fp16)
        uint32_t qh[2][4], ql[2][4];
#pragma unroll
        for (int ks = 0; ks < 2; ks++) {
            const int f0 = ks * 16 + 2 * t4;
            float2 x00 = *(const float2*)(q0 + f0);
            float2 x10 = *(const float2*)(q1 + f0);
            float2 x01 = *(const float2*)(q0 + f0 + 8);
            float2 x11 = *(const float2*)(q1 + f0 + 8);
            x00.x *= QSCALE; x00.y *= QSCALE; x10.x *= QSCALE; x10.y *= QSCALE;
            x01.x *= QSCALE; x01.y *= QSCALE; x11.x *= QSCALE; x11.y *= QSCALE;
            split_pack(x00.x, x00.y, qh[ks][0], ql[ks][0]);
            split_pack(x10.x, x10.y, qh[ks][1], ql[ks][1]);
            split_pack(x01.x, x01.y, qh[ks][2], ql[ks][2]);
            split_pack(x11.x, x11.y, qh[ks][3], ql[ks][3]);
        }

        float c[8][4];
        uint32_t hc[8][2];
#pragma unroll
        for (int nt = 0; nt < 8; nt++) {
            c[nt][0] = c[nt][1] = c[nt][2] = c[nt][3] = 0.f;
            hc[nt][0] = 0u; hc[nt][1] = 0u;
        }
#pragma unroll
        for (int nt = 0; nt < 8; nt++) {
            int cn = nt * 8 + gid;
#pragma unroll
            for (int ks = 0; ks < 2; ks++) {
                int cp = ks * 8 + t4;
                uint32_t bh0 = KH[cn * 17 + cp], bh1 = KH[cn * 17 + cp + 4];
                uint32_t bl0 = KL[cn * 17 + cp], bl1 = KL[cn * 17 + cp + 4];
                mma_f32(c[nt], qh[ks][0], qh[ks][1], qh[ks][2], qh[ks][3], bh0, bh1);
                mma_f16(hc[nt], qh[ks][0], qh[ks][1], qh[ks][2], qh[ks][3], bl0, bl1);
                mma_f16(hc[nt], ql[ks][0], ql[ks][1], ql[ks][2], ql[ks][3], bh0, bh1);
            }
        }

        // fold f16 corrections into fp32 scores
#pragma unroll
        for (int nt = 0; nt < 8; nt++) {
            float2 g0 = h2f(hc[nt][0]);
            float2 g1 = h2f(hc[nt][1]);
            c[nt][0] += g0.x; c[nt][1] += g0.y;
            c[nt][2] += g1.x; c[nt][3] += g1.y;
        }

        // bias + shift mask + padding mask
        const int ih0 = rc0 / WS, iw0 = rc0 % WS;
        const int ih1 = rc1 / WS, iw1 = rc1 % WS;
        int hr, wr, rh, rw;
        hr = hbase + ih0; wr = wbase + iw0;
        rh = (hr < 49) ? 0 : ((hr < 53) ? 1 : 2); rw = (wr < 49) ? 0 : ((wr < 53) ? 1 : 2);
        const int rg0 = rh * 3 + rw;
        hr = hbase + ih1; wr = wbase + iw1;
        rh = (hr < 49) ? 0 : ((hr < 53) ? 1 : 2); rw = (wr < 49) ? 0 : ((wr < 53) ? 1 : 2);
        const int rg1 = rh * 3 + rw;

#pragma unroll
        for (int nt = 0; nt < 8; nt++) {
#pragma unroll
            for (int jc = 0; jc < 2; jc++) {
                int j = nt * 8 + 2 * t4 + jc;
                if (j < NTOK) {
                    int jh = j / WS, jw = j % WS;
                    int jhr = hbase + jh, jwr = wbase + jw;
                    int rjh = (jhr < 49) ? 0 : ((jhr < 53) ? 1 : 2);
                    int rjw = (jwr < 49) ? 0 : ((jwr < 53) ? 1 : 2);
                    int rgj = rjh * 3 + rjw;
                    float b0 = TBL[(ih0 - jh + 6) * 13 + (iw0 - jw + 6)];
                    float b1 = TBL[(ih1 - jh + 6) * 13 + (iw1 - jw + 6)];
                    if (rg0 != rgj) b0 -= 100.f;
                    if (rg1 != rgj) b1 -= 100.f;
                    c[nt][jc] += b0;
                    c[nt][2 + jc] += b1;
                } else {
                    c[nt][jc] = -1e30f;
                    c[nt][2 + jc] = -1e30f;
                }
            }
        }

        // softmax over t4 quad
        float m0 = -1e30f, m1 = -1e30f;
#pragma unroll
        for (int nt = 0; nt < 8; nt++) {
            m0 = fmaxf(m0, fmaxf(c[nt][0], c[nt][1]));
            m1 = fmaxf(m1, fmaxf(c[nt][2], c[nt][3]));
        }
        m0 = fmaxf(m0, __shfl_xor_sync(0xffffffffu, m0, 1));
        m0 = fmaxf(m0, __shfl_xor_sync(0xffffffffu, m0, 2));
        m1 = fmaxf(m1, __shfl_xor_sync(0xffffffffu, m1, 1));
        m1 = fmaxf(m1, __shfl_xor_sync(0xffffffffu, m1, 2));
        float s0 = 0.f, s1 = 0.f;
#pragma unroll
        for (int nt = 0; nt < 8; nt++) {
            c[nt][0] = __expf(c[nt][0] - m0); s0 += c[nt][0];
            c[nt][1] = __expf(c[nt][1] - m0); s0 += c[nt][1];
            c[nt][2] = __expf(c[nt][2] - m1); s1 += c[nt][2];
            c[nt][3] = __expf(c[nt][3] - m1); s1 += c[nt][3];
        }
        s0 += __shfl_xor_sync(0xffffffffu, s0, 1);
        s0 += __shfl_xor_sync(0xffffffffu, s0, 2);
        s1 += __shfl_xor_sync(0xffffffffu, s1, 1);
        s1 += __shfl_xor_sync(0xffffffffu, s1, 2);
        const float inv0 = 1.f / s0, inv1 = 1.f / s1;
#pragma unroll
        for (int nt = 0; nt < 8; nt++) {
            c[nt][0] *= inv0; c[nt][1] *= inv0;
            c[nt][2] *= inv1; c[nt][3] *= inv1;
        }

        // O += P V (hi->f32 acc, corrections -> f16 acc)
#pragma unroll
        for (int kt = 0; kt < 4; kt++) {
            uint32_t ph[4], pl[4];
            split_pack(c[2 * kt][0],     c[2 * kt][1],     ph[0], pl[0]);
            split_pack(c[2 * kt][2],     c[2 * kt][3],     ph[1], pl[1]);
            split_pack(c[2 * kt + 1][0], c[2 * kt + 1][1], ph[2], pl[2]);
            split_pack(c[2 * kt + 1][2], c[2 * kt + 1][3], ph[3], pl[3]);
#pragma unroll
            for (int nt = 0; nt < 4; nt++) {
                int dn = nt * 8 + gid;
                uint32_t bh0 = VTH[dn * 33 + kt * 8 + t4];
                uint32_t bh1 = VTH[dn * 33 + kt * 8 + t4 + 4];
                uint32_t bl0 = VTL[dn * 33 + kt * 8 + t4];
                uint32_t bl1 = VTL[dn * 33 + kt * 8 + t4 + 4];
                mma_f32(o[mt][nt], ph[0], ph[1], ph[2], ph[3], bh0, bh1);
                mma_f16(ho[mt][nt], ph[0], ph[1], ph[2], ph[3], bl0, bl1);
                mma_f16(ho[mt][nt], pl[0], pl[1], pl[2], pl[3], bh0, bh1);
            }
        }
    }

    // store O (fold f16 corrections)
#pragma unroll
    for (int mt = 0; mt < 4; mt++) {
        int i0 = mt * 16 + gid, i1 = i0 + 8;
#pragma unroll
        for (int nt = 0; nt < 4; nt++) {
            int d = nt * 8 + 2 * t4;
            float2 g0 = h2f(ho[mt][nt][0]);
            float2 g1 = h2f(ho[mt][nt][1]);
            if (i0 < NTOK) {
                float2 r;
                r.x = o[mt][nt][0] + g0.x;
                r.y = o[mt][nt][1] + g0.y;
                *(float2*)(out + ((size_t)win * NTOK + i0) * CH + head * HD + d) = r;
            }
            if (i1 < NTOK) {
                float2 r;
                r.x = o[mt][nt][2] + g1.x;
                r.y = o[mt][nt][3] + g1.y;
                *(float2*)(out + ((size_t)win * NTOK + i1) * CH + head * HD + d) = r;
            }
        }
    }
}

extern "C" void kernel_launch(void* const* d_in, const int* in_sizes, int n_in,
                              void* d_out, int out_size) {
    const float* x      = (const float*)d_in[0];
    const float* qkv_w  = (const float*)d_in[1];
    const float* qkv_b  = (const float*)d_in[2];
    const float* proj_w = (const float*)d_in[3];
    const float* proj_b = (const float*)d_in[4];
    const float* table  = (const float*)d_in[5];
    float* out = (float*)d_out;

    float* qkv_buf;
    float* attn_buf;
    cudaGetSymbolAddress((void**)&qkv_buf, g_qkv);
    cudaGetSymbolAddress((void**)&attn_buf, g_attnout);

    cudaFuncSetAttribute(tc_gemm<0>, cudaFuncAttributeMaxDynamicSharedMemorySize, SMEM_GEMM);
    cudaFuncSetAttribute(tc_gemm<1>, cudaFuncAttributeMaxDynamicSharedMemorySize, SMEM_GEMM);

    dim3 g1(QKV_N / 128, M_TOTAL / 128);   // (6, 1568)
    tc_gemm<0><<<g1, 512, SMEM_GEMM>>>(x, qkv_w, qkv_b, qkv_buf);

    attn_mma_kernel<<<BATCH * NWIN * NHEAD, 32>>>(qkv_buf, table, attn_buf);

    dim3 g3(CH / 128, M_TOTAL / 128);      // (2, 1568)
    tc_gemm<1><<<g3, 512, SMEM_GEMM>>>(attn_buf, proj_w, proj_b, out);
}

// round 11
// speedup vs baseline: 1.6553x; 1.6553x over previous
#include <cuda_runtime.h>
#include <cuda_fp16.h>
#include <cstdint>

// Problem constants (B=64, H=W=56, C=256, heads=8, hd=32, ws=7, shift=3)
#define IMG 56
#define CH 256
#define NHEAD 8
#define HD 32
#define WS 7
#define NWIN 64
#define NTOK 49
#define BATCH 64
#define M_TOTAL (BATCH * IMG * IMG)   // 200704
#define QKV_N 768
#define QSCALE 0.17677669529663687f

// Scratch
__device__ float g_qkv[(size_t)M_TOTAL * QKV_N];     // window-order [m, 768]
__device__ float g_attnout[(size_t)M_TOTAL * CH];    // window-order [m, 256]

// ---- index helper ------------------------------------------------------
__device__ __forceinline__ int gather_src_row(int m) {
    int win = m / NTOK, n = m - win * NTOK;
    int b = win >> 6, wl = win & 63;
    int hr = (wl >> 3) * WS + n / WS;
    int wr = (wl & 7) * WS + n % WS;
    int h = hr + 3; if (h >= IMG) h -= IMG;
    int w = wr + 3; if (w >= IMG) w -= IMG;
    return (b * IMG + h) * IMG + w;
}

__device__ __forceinline__ uint32_t pack_h2(float a, float b) {
    __half2 h = __floats2half2_rn(a, b);
    return *reinterpret_cast<uint32_t*>(&h);
}

__device__ __forceinline__ void mma16816(float* c,
    uint32_t a0, uint32_t a1, uint32_t a2, uint32_t a3,
    uint32_t b0, uint32_t b1) {
    asm volatile(
        "mma.sync.aligned.m16n8k16.row.col.f32.f16.f16.f32 "
        "{%0,%1,%2,%3}, {%4,%5,%6,%7}, {%8,%9}, {%0,%1,%2,%3};"
        : "+f"(c[0]), "+f"(c[1]), "+f"(c[2]), "+f"(c[3])
        : "r"(a0), "r"(a1), "r"(a2), "r"(a3), "r"(b0), "r"(b1));
}

// ---- HMMA GEMM: 128x256 tile, 512 threads (16 warps of 32x64), BK=32 ---
// single-product fp16, fp32 accumulate
#define BK 32
#define SA 40
#define A_ELEMS (128 * SA)                 // 5120 halfs
#define B_ELEMS (256 * SA)                 // 10240 halfs
#define STG_ELEMS (A_ELEMS + B_ELEMS)      // 15360 per stage
#define SMEM_GEMM (2 * STG_ELEMS * 2)      // 61440 bytes

template <int MODE>
__global__ void __launch_bounds__(512, 1) tc_gemm(
    const float* __restrict__ A, const float* __restrict__ W,
    const float* __restrict__ bias, float* __restrict__ out)
{
    extern __shared__ __half sm[];
    const int tid = threadIdx.x;
    const int wid = tid >> 5;
    const int lane = tid & 31;
    const int gid = lane >> 2;
    const int t4 = lane & 3;
    const int wm = wid & 3;          // 4 row groups of 32
    const int wn = wid >> 2;         // 4 col groups of 64
    const int bm = blockIdx.y * 128;
    const int bn = blockIdx.x * 256;
    const int OUT_STRIDE = (MODE == 0) ? QKV_N : CH;

    // loaders: A row = tid>>2 (0..127), 8 k's; B row = tid>>1 (0..255), 16 k's
    const int arow = tid >> 2;
    const int ak = (tid & 3) * 8;
    const int brow = tid >> 1;
    const int bk = (tid & 1) * 16;
    const float* Arow = (MODE == 0)
        ? (A + (size_t)gather_src_row(bm + arow) * CH)
        : (A + (size_t)(bm + arow) * CH);
    const float* Brow = W + (size_t)(bn + brow) * CH;

    float acc[2][8][4];
#pragma unroll
    for (int mt = 0; mt < 2; mt++)
#pragma unroll
        for (int nt = 0; nt < 8; nt++)
#pragma unroll
            for (int r = 0; r < 4; r++) acc[mt][nt][r] = 0.f;

    auto Abuf = [&](int st) { return sm + st * STG_ELEMS; };
    auto Bbuf = [&](int st) { return sm + st * STG_ELEMS + A_ELEMS; };

    auto sts_stage = [&](int st, const float4* av, const float4* bv) {
        uint32_t* pa = (uint32_t*)(Abuf(st) + arow * SA + ak);
        pa[0] = pack_h2(av[0].x, av[0].y);
        pa[1] = pack_h2(av[0].z, av[0].w);
        pa[2] = pack_h2(av[1].x, av[1].y);
        pa[3] = pack_h2(av[1].z, av[1].w);
        uint32_t* pb = (uint32_t*)(Bbuf(st) + brow * SA + bk);
#pragma unroll
        for (int j = 0; j < 4; j++) {
            pb[2 * j]     = pack_h2(bv[j].x, bv[j].y);
            pb[2 * j + 1] = pack_h2(bv[j].z, bv[j].w);
        }
    };

    float4 av[2], bv[4];
    av[0] = *(const float4*)(Arow + ak);
    av[1] = *(const float4*)(Arow + ak + 4);
#pragma unroll
    for (int j = 0; j < 4; j++) bv[j] = *(const float4*)(Brow + bk + 4 * j);
    sts_stage(0, av, bv);
    __syncthreads();

    const int NSTAGE = CH / BK;   // 8
    for (int s = 0; s < NSTAGE; s++) {
        const int p = s & 1;
        if (s + 1 < NSTAGE) {
            const int k0 = (s + 1) * BK;
            av[0] = *(const float4*)(Arow + k0 + ak);
            av[1] = *(const float4*)(Arow + k0 + ak + 4);
#pragma unroll
            for (int j = 0; j < 4; j++) bv[j] = *(const float4*)(Brow + k0 + bk + 4 * j);
        }

        const __half* Ah = Abuf(p);
        const __half* Bh = Bbuf(p);
#pragma unroll
        for (int ksub = 0; ksub < 2; ksub++) {
            const int kk = ksub * 16 + 2 * t4;
            uint32_t ah[2][4];
#pragma unroll
            for (int mt = 0; mt < 2; mt++) {
                int r = wm * 32 + mt * 16 + gid;
                ah[mt][0] = *(const uint32_t*)(Ah + r * SA + kk);
                ah[mt][1] = *(const uint32_t*)(Ah + (r + 8) * SA + kk);
                ah[mt][2] = *(const uint32_t*)(Ah + r * SA + kk + 8);
                ah[mt][3] = *(const uint32_t*)(Ah + (r + 8) * SA + kk + 8);
            }
#pragma unroll
            for (int nt = 0; nt < 8; nt++) {
                int c = wn * 64 + nt * 8 + gid;
                uint32_t b0 = *(const uint32_t*)(Bh + c * SA + kk);
                uint32_t b1 = *(const uint32_t*)(Bh + c * SA + kk + 8);
                mma16816(acc[0][nt], ah[0][0], ah[0][1], ah[0][2], ah[0][3], b0, b1);
                mma16816(acc[1][nt], ah[1][0], ah[1][1], ah[1][2], ah[1][3], b0, b1);
            }
        }
        __syncthreads();
        if (s + 1 < NSTAGE) {
            sts_stage((s + 1) & 1, av, bv);
            __syncthreads();
        }
    }

#pragma unroll
    for (int mt = 0; mt < 2; mt++) {
        int m1 = bm + wm * 32 + mt * 16 + gid;
        int m2 = m1 + 8;
        float* d1;
        float* d2;
        if (MODE == 0) {
            d1 = out + (size_t)m1 * OUT_STRIDE;
            d2 = out + (size_t)m2 * OUT_STRIDE;
        } else {
            d1 = out + (size_t)gather_src_row(m1) * OUT_STRIDE;
            d2 = out + (size_t)gather_src_row(m2) * OUT_STRIDE;
        }
#pragma unroll
        for (int nt = 0; nt < 8; nt++) {
            int n = bn + wn * 64 + nt * 8 + 2 * t4;
            float2 bv2 = *(const float2*)(bias + n);
            float2 r1, r2;
            r1.x = acc[mt][nt][0] + bv2.x; r1.y = acc[mt][nt][1] + bv2.y;
            r2.x = acc[mt][nt][2] + bv2.x; r2.y = acc[mt][nt][3] + bv2.y;
            *(float2*)(d1 + n) = r1;
            *(float2*)(d2 + n) = r2;
        }
    }
}

// ---- HMMA window attention: one warp per (window, head), fp16 single ---
__global__ void __launch_bounds__(32) attn_mma_kernel(
    const float* __restrict__ qkv, const float* __restrict__ table,
    float* __restrict__ out)
{
    const int blk = blockIdx.x;
    const int win = blk >> 3;
    const int head = blk & 7;
    const int lane = threadIdx.x;
    const int gid = lane >> 2;
    const int t4 = lane & 3;
    const int wl = win & 63;
    const int hbase = (wl >> 3) * WS;
    const int wbase = (wl & 7) * WS;

    __shared__ uint32_t KH[64 * 17];
    __shared__ uint32_t VTH[32 * 33];
    __shared__ float TBL[169];

    for (int t = lane; t < 169; t += 32) TBL[t] = table[t * NHEAD + head];

    const float* base = qkv + (size_t)win * NTOK * QKV_N + head * HD;

    // K: cooperative coalesced load, fp16 pack, zero padding rows
    for (int r = lane; r < 64; r += 32) {
        bool valid = r < NTOK;
        const float* p = base + (size_t)(valid ? r : 0) * QKV_N + 256;
#pragma unroll
        for (int j = 0; j < 8; j++) {
            float4 kv = valid ? *(const float4*)(p + 4 * j) : make_float4(0, 0, 0, 0);
            KH[r * 17 + 2 * j]     = pack_h2(kv.x, kv.y);
            KH[r * 17 + 2 * j + 1] = pack_h2(kv.z, kv.w);
        }
    }

    // V transposed directly from gmem: lane = d, coalesced per token
    const float* vbase = base + 512;
#pragma unroll 4
    for (int tp = 0; tp < 32; tp++) {
        int t0 = 2 * tp, t1 = 2 * tp + 1;
        float a = (t0 < NTOK) ? vbase[(size_t)t0 * QKV_N + lane] : 0.f;
        float b = (t1 < NTOK) ? vbase[(size_t)t1 * QKV_N + lane] : 0.f;
        VTH[lane * 33 + tp] = pack_h2(a, b);
    }
    __syncwarp();

    float o[4][4][4];
#pragma unroll
    for (int a = 0; a < 4; a++)
#pragma unroll
        for (int b = 0; b < 4; b++)
#pragma unroll
            for (int r = 0; r < 4; r++) o[a][b][r] = 0.f;

#pragma unroll
    for (int mt = 0; mt < 4; mt++) {
        const int r0 = mt * 16 + gid;
        const int rc0 = min(r0, NTOK - 1);
        const int rc1 = min(r0 + 8, NTOK - 1);
        const float* q0 = base + (size_t)rc0 * QKV_N;
        const float* q1 = base + (size_t)rc1 * QKV_N;

        // Q A-fragments straight from gmem (scaled, packed fp16)
        uint32_t qh[2][4];
#pragma unroll
        for (int ks = 0; ks < 2; ks++) {
            const int f0 = ks * 16 + 2 * t4;
            float2 x00 = *(const float2*)(q0 + f0);
            float2 x10 = *(const float2*)(q1 + f0);
            float2 x01 = *(const float2*)(q0 + f0 + 8);
            float2 x11 = *(const float2*)(q1 + f0 + 8);
            qh[ks][0] = pack_h2(x00.x * QSCALE, x00.y * QSCALE);
            qh[ks][1] = pack_h2(x10.x * QSCALE, x10.y * QSCALE);
            qh[ks][2] = pack_h2(x01.x * QSCALE, x01.y * QSCALE);
            qh[ks][3] = pack_h2(x11.x * QSCALE, x11.y * QSCALE);
        }

        float c[8][4];
#pragma unroll
        for (int nt = 0; nt < 8; nt++) { c[nt][0] = c[nt][1] = c[nt][2] = c[nt][3] = 0.f; }
#pragma unroll
        for (int nt = 0; nt < 8; nt++) {
            int cn = nt * 8 + gid;
#pragma unroll
            for (int ks = 0; ks < 2; ks++) {
                int cp = ks * 8 + t4;
                uint32_t b0 = KH[cn * 17 + cp], b1 = KH[cn * 17 + cp + 4];
                mma16816(c[nt], qh[ks][0], qh[ks][1], qh[ks][2], qh[ks][3], b0, b1);
            }
        }

        // bias + shift mask + padding mask
        const int ih0 = rc0 / WS, iw0 = rc0 % WS;
        const int ih1 = rc1 / WS, iw1 = rc1 % WS;
        int hr, wr, rh, rw;
        hr = hbase + ih0; wr = wbase + iw0;
        rh = (hr < 49) ? 0 : ((hr < 53) ? 1 : 2); rw = (wr < 49) ? 0 : ((wr < 53) ? 1 : 2);
        const int rg0 = rh * 3 + rw;
        hr = hbase + ih1; wr = wbase + iw1;
        rh = (hr < 49) ? 0 : ((hr < 53) ? 1 : 2); rw = (wr < 49) ? 0 : ((wr < 53) ? 1 : 2);
        const int rg1 = rh * 3 + rw;

#pragma unroll
        for (int nt = 0; nt < 8; nt++) {
#pragma unroll
            for (int jc = 0; jc < 2; jc++) {
                int j = nt * 8 + 2 * t4 + jc;
                if (j < NTOK) {
                    int jh = j / WS, jw = j % WS;
                    int jhr = hbase + jh, jwr = wbase + jw;
                    int rjh = (jhr < 49) ? 0 : ((jhr < 53) ? 1 : 2);
                    int rjw = (jwr < 49) ? 0 : ((jwr < 53) ? 1 : 2);
                    int rgj = rjh * 3 + rjw;
                    float b0 = TBL[(ih0 - jh + 6) * 13 + (iw0 - jw + 6)];
                    float b1 = TBL[(ih1 - jh + 6) * 13 + (iw1 - jw + 6)];
                    if (rg0 != rgj) b0 -= 100.f;
                    if (rg1 != rgj) b1 -= 100.f;
                    c[nt][jc] += b0;
                    c[nt][2 + jc] += b1;
                } else {
                    c[nt][jc] = -1e30f;
                    c[nt][2 + jc] = -1e30f;
                }
            }
        }

        // softmax over t4 quad
        float m0 = -1e30f, m1 = -1e30f;
#pragma unroll
        for (int nt = 0; nt < 8; nt++) {
            m0 = fmaxf(m0, fmaxf(c[nt][0], c[nt][1]));
            m1 = fmaxf(m1, fmaxf(c[nt][2], c[nt][3]));
        }
        m0 = fmaxf(m0, __shfl_xor_sync(0xffffffffu, m0, 1));
        m0 = fmaxf(m0, __shfl_xor_sync(0xffffffffu, m0, 2));
        m1 = fmaxf(m1, __shfl_xor_sync(0xffffffffu, m1, 1));
        m1 = fmaxf(m1, __shfl_xor_sync(0xffffffffu, m1, 2));
        float s0 = 0.f, s1 = 0.f;
#pragma unroll
        for (int nt = 0; nt < 8; nt++) {
            c[nt][0] = __expf(c[nt][0] - m0); s0 += c[nt][0];
            c[nt][1] = __expf(c[nt][1] - m0); s0 += c[nt][1];
            c[nt][2] = __expf(c[nt][2] - m1); s1 += c[nt][2];
            c[nt][3] = __expf(c[nt][3] - m1); s1 += c[nt][3];
        }
        s0 += __shfl_xor_sync(0xffffffffu, s0, 1);
        s0 += __shfl_xor_sync(0xffffffffu, s0, 2);
        s1 += __shfl_xor_sync(0xffffffffu, s1, 1);
        s1 += __shfl_xor_sync(0xffffffffu, s1, 2);
        const float inv0 = 1.f / s0, inv1 = 1.f / s1;
#pragma unroll
        for (int nt = 0; nt < 8; nt++) {
            c[nt][0] *= inv0; c[nt][1] *= inv0;
            c[nt][2] *= inv1; c[nt][3] *= inv1;
        }

        // O += P V
#pragma unroll
        for (int kt = 0; kt < 4; kt++) {
            uint32_t ph[4];
            ph[0] = pack_h2(c[2 * kt][0],     c[2 * kt][1]);
            ph[1] = pack_h2(c[2 * kt][2],     c[2 * kt][3]);
            ph[2] = pack_h2(c[2 * kt + 1][0], c[2 * kt + 1][1]);
            ph[3] = pack_h2(c[2 * kt + 1][2], c[2 * kt + 1][3]);
#pragma unroll
            for (int nt = 0; nt < 4; nt++) {
                int dn = nt * 8 + gid;
                uint32_t b0 = VTH[dn * 33 + kt * 8 + t4];
                uint32_t b1 = VTH[dn * 33 + kt * 8 + t4 + 4];
                mma16816(o[mt][nt], ph[0], ph[1], ph[2], ph[3], b0, b1);
            }
        }
    }

    // store O
#pragma unroll
    for (int mt = 0; mt < 4; mt++) {
        int i0 = mt * 16 + gid, i1 = i0 + 8;
#pragma unroll
        for (int nt = 0; nt < 4; nt++) {
            int d = nt * 8 + 2 * t4;
            if (i0 < NTOK) {
                float2 r; r.x = o[mt][nt][0]; r.y = o[mt][nt][1];
                *(float2*)(out + ((size_t)win * NTOK + i0) * CH + head * HD + d) = r;
            }
            if (i1 < NTOK) {
                float2 r; r.x = o[mt][nt][2]; r.y = o[mt][nt][3];
                *(float2*)(out + ((size_t)win * NTOK + i1) * CH + head * HD + d) = r;
            }
        }
    }
}

extern "C" void kernel_launch(void* const* d_in, const int* in_sizes, int n_in,
                              void* d_out, int out_size) {
    const float* x      = (const float*)d_in[0];
    const float* qkv_w  = (const float*)d_in[1];
    const float* qkv_b  = (const float*)d_in[2];
    const float* proj_w = (const float*)d_in[3];
    const float* proj_b = (const float*)d_in[4];
    const float* table  = (const float*)d_in[5];
    float* out = (float*)d_out;

    float* qkv_buf;
    float* attn_buf;
    cudaGetSymbolAddress((void**)&qkv_buf, g_qkv);
    cudaGetSymbolAddress((void**)&attn_buf, g_attnout);

    cudaFuncSetAttribute(tc_gemm<0>, cudaFuncAttributeMaxDynamicSharedMemorySize, SMEM_GEMM);
    cudaFuncSetAttribute(tc_gemm<1>, cudaFuncAttributeMaxDynamicSharedMemorySize, SMEM_GEMM);

    dim3 g1(QKV_N / 256, M_TOTAL / 128);   // (3, 1568)
    tc_gemm<0><<<g1, 512, SMEM_GEMM>>>(x, qkv_w, qkv_b, qkv_buf);

    attn_mma_kernel<<<BATCH * NWIN * NHEAD, 32>>>(qkv_buf, table, attn_buf);

    dim3 g3(CH / 256, M_TOTAL / 128);      // (1, 1568)
    tc_gemm<1><<<g3, 512, SMEM_GEMM>>>(attn_buf, proj_w, proj_b, out);
}

// round 12
// speedup vs baseline: 1.7712x; 1.0700x over previous
#include <cuda_runtime.h>
#include <cuda_fp16.h>
#include <cstdint>

// Problem constants (B=64, H=W=56, C=256, heads=8, hd=32, ws=7, shift=3)
#define IMG 56
#define CH 256
#define NHEAD 8
#define HD 32
#define WS 7
#define NWIN 64
#define NTOK 49
#define BATCH 64
#define M_TOTAL (BATCH * IMG * IMG)   // 200704
#define QKV_N 768
#define QSCALE 0.17677669529663687f

// Scratch (fp16 end-to-end between kernels)
__device__ __half g_qkv[(size_t)M_TOTAL * QKV_N];     // window-order [m, 768], q pre-scaled
__device__ __half g_attnout[(size_t)M_TOTAL * CH];    // window-order [m, 256]

// ---- index helper ------------------------------------------------------
__device__ __forceinline__ int gather_src_row(int m) {
    int win = m / NTOK, n = m - win * NTOK;
    int b = win >> 6, wl = win & 63;
    int hr = (wl >> 3) * WS + n / WS;
    int wr = (wl & 7) * WS + n % WS;
    int h = hr + 3; if (h >= IMG) h -= IMG;
    int w = wr + 3; if (w >= IMG) w -= IMG;
    return (b * IMG + h) * IMG + w;
}

__device__ __forceinline__ uint32_t pack_h2(float a, float b) {
    __half2 h = __floats2half2_rn(a, b);
    return *reinterpret_cast<uint32_t*>(&h);
}

__device__ __forceinline__ void mma16816(float* c,
    uint32_t a0, uint32_t a1, uint32_t a2, uint32_t a3,
    uint32_t b0, uint32_t b1) {
    asm volatile(
        "mma.sync.aligned.m16n8k16.row.col.f32.f16.f16.f32 "
        "{%0,%1,%2,%3}, {%4,%5,%6,%7}, {%8,%9}, {%0,%1,%2,%3};"
        : "+f"(c[0]), "+f"(c[1]), "+f"(c[2]), "+f"(c[3])
        : "r"(a0), "r"(a1), "r"(a2), "r"(a3), "r"(b0), "r"(b1));
}

// ---- HMMA GEMM: 128x256 tile, 512 threads (16 warps of 32x64), BK=32 ---
// MODE 0: A = x fp32 (gathered), out = g_qkv (__half, QSCALE folded for n<256)
// MODE 1: A = g_attnout (__half), out = d_out fp32 (scattered)
#define BK 32
#define SA 40
#define A_ELEMS (128 * SA)
#define B_ELEMS (256 * SA)
#define STG_ELEMS (A_ELEMS + B_ELEMS)
#define SMEM_GEMM (2 * STG_ELEMS * 2)      // 61440 bytes

template <int MODE>
__global__ void __launch_bounds__(512, 1) tc_gemm(
    const void* __restrict__ Aptr, const float* __restrict__ W,
    const float* __restrict__ bias, void* __restrict__ outptr)
{
    extern __shared__ __half sm[];
    const int tid = threadIdx.x;
    const int wid = tid >> 5;
    const int lane = tid & 31;
    const int gid = lane >> 2;
    const int t4 = lane & 3;
    const int wm = wid & 3;
    const int wn = wid >> 2;
    const int bm = blockIdx.y * 128;
    const int bn = blockIdx.x * 256;

    // loaders: A row = tid>>2 (0..127), 8 k's; B row = tid>>1 (0..255), 16 k's
    const int arow = tid >> 2;
    const int ak = (tid & 3) * 8;
    const int brow = tid >> 1;
    const int bk = (tid & 1) * 16;
    const float* Arow_f = nullptr;
    const __half* Arow_h = nullptr;
    if (MODE == 0) Arow_f = (const float*)Aptr + (size_t)gather_src_row(bm + arow) * CH;
    else           Arow_h = (const __half*)Aptr + (size_t)(bm + arow) * CH;
    const float* Brow = W + (size_t)(bn + brow) * CH;

    float acc[2][8][4];
#pragma unroll
    for (int mt = 0; mt < 2; mt++)
#pragma unroll
        for (int nt = 0; nt < 8; nt++)
#pragma unroll
            for (int r = 0; r < 4; r++) acc[mt][nt][r] = 0.f;

    auto Abuf = [&](int st) { return sm + st * STG_ELEMS; };
    auto Bbuf = [&](int st) { return sm + st * STG_ELEMS + A_ELEMS; };

    float4 avf[2]; uint4 avh; float4 bv[4];

    auto lds_inputs = [&](int k0) {
        if (MODE == 0) {
            avf[0] = *(const float4*)(Arow_f + k0 + ak);
            avf[1] = *(const float4*)(Arow_f + k0 + ak + 4);
        } else {
            avh = *(const uint4*)(Arow_h + k0 + ak);
        }
#pragma unroll
        for (int j = 0; j < 4; j++) bv[j] = *(const float4*)(Brow + k0 + bk + 4 * j);
    };

    auto sts_stage = [&](int st) {
        uint32_t* pa = (uint32_t*)(Abuf(st) + arow * SA + ak);
        if (MODE == 0) {
            pa[0] = pack_h2(avf[0].x, avf[0].y);
            pa[1] = pack_h2(avf[0].z, avf[0].w);
            pa[2] = pack_h2(avf[1].x, avf[1].y);
            pa[3] = pack_h2(avf[1].z, avf[1].w);
        } else {
            pa[0] = avh.x; pa[1] = avh.y; pa[2] = avh.z; pa[3] = avh.w;
        }
        uint32_t* pb = (uint32_t*)(Bbuf(st) + brow * SA + bk);
#pragma unroll
        for (int j = 0; j < 4; j++) {
            pb[2 * j]     = pack_h2(bv[j].x, bv[j].y);
            pb[2 * j + 1] = pack_h2(bv[j].z, bv[j].w);
        }
    };

    lds_inputs(0);
    sts_stage(0);
    __syncthreads();

    const int NSTAGE = CH / BK;   // 8
    for (int s = 0; s < NSTAGE; s++) {
        const int p = s & 1;
        if (s + 1 < NSTAGE) lds_inputs((s + 1) * BK);

        const __half* Ah = Abuf(p);
        const __half* Bh = Bbuf(p);
#pragma unroll
        for (int ksub = 0; ksub < 2; ksub++) {
            const int kk = ksub * 16 + 2 * t4;
            uint32_t ah[2][4];
#pragma unroll
            for (int mt = 0; mt < 2; mt++) {
                int r = wm * 32 + mt * 16 + gid;
                ah[mt][0] = *(const uint32_t*)(Ah + r * SA + kk);
                ah[mt][1] = *(const uint32_t*)(Ah + (r + 8) * SA + kk);
                ah[mt][2] = *(const uint32_t*)(Ah + r * SA + kk + 8);
                ah[mt][3] = *(const uint32_t*)(Ah + (r + 8) * SA + kk + 8);
            }
#pragma unroll
            for (int nt = 0; nt < 8; nt++) {
                int c = wn * 64 + nt * 8 + gid;
                uint32_t b0 = *(const uint32_t*)(Bh + c * SA + kk);
                uint32_t b1 = *(const uint32_t*)(Bh + c * SA + kk + 8);
                mma16816(acc[0][nt], ah[0][0], ah[0][1], ah[0][2], ah[0][3], b0, b1);
                mma16816(acc[1][nt], ah[1][0], ah[1][1], ah[1][2], ah[1][3], b0, b1);
            }
        }
        __syncthreads();
        if (s + 1 < NSTAGE) {
            sts_stage((s + 1) & 1);
            __syncthreads();
        }
    }

    // epilogue
#pragma unroll
    for (int mt = 0; mt < 2; mt++) {
        int m1 = bm + wm * 32 + mt * 16 + gid;
        int m2 = m1 + 8;
        if (MODE == 0) {
            __half* d1 = (__half*)outptr + (size_t)m1 * QKV_N;
            __half* d2 = (__half*)outptr + (size_t)m2 * QKV_N;
#pragma unroll
            for (int nt = 0; nt < 8; nt++) {
                int n = bn + wn * 64 + nt * 8 + 2 * t4;
                float2 bv2 = *(const float2*)(bias + n);
                float sc = (n < 256) ? QSCALE : 1.0f;   // fold q scaling
                *(uint32_t*)(d1 + n) = pack_h2((acc[mt][nt][0] + bv2.x) * sc,
                                               (acc[mt][nt][1] + bv2.y) * sc);
                *(uint32_t*)(d2 + n) = pack_h2((acc[mt][nt][2] + bv2.x) * sc,
                                               (acc[mt][nt][3] + bv2.y) * sc);
            }
        } else {
            float* d1 = (float*)outptr + (size_t)gather_src_row(m1) * CH;
            float* d2 = (float*)outptr + (size_t)gather_src_row(m2) * CH;
#pragma unroll
            for (int nt = 0; nt < 8; nt++) {
                int n = bn + wn * 64 + nt * 8 + 2 * t4;
                float2 bv2 = *(const float2*)(bias + n);
                float2 r1, r2;
                r1.x = acc[mt][nt][0] + bv2.x; r1.y = acc[mt][nt][1] + bv2.y;
                r2.x = acc[mt][nt][2] + bv2.x; r2.y = acc[mt][nt][3] + bv2.y;
                *(float2*)(d1 + n) = r1;
                *(float2*)(d2 + n) = r2;
            }
        }
    }
}

// ---- HMMA window attention: one warp per (window, head), fp16 I/O ------
__global__ void __launch_bounds__(32) attn_mma_kernel(
    const __half* __restrict__ qkv, const float* __restrict__ table,
    __half* __restrict__ out)
{
    const int blk = blockIdx.x;
    const int win = blk >> 3;
    const int head = blk & 7;
    const int lane = threadIdx.x;
    const int gid = lane >> 2;
    const int t4 = lane & 3;
    const int wl = win & 63;
    const int hbase = (wl >> 3) * WS;
    const int wbase = (wl & 7) * WS;

    __shared__ uint32_t KH[64 * 17];
    __shared__ uint32_t VTH[32 * 33];
    __shared__ float TBL[169];

    for (int t = lane; t < 169; t += 32) TBL[t] = table[t * NHEAD + head];

    const __half* base = qkv + (size_t)win * NTOK * QKV_N + head * HD;

    // K: raw fp16 copy into smem (uint4 = 8 halfs), zero padding rows
    for (int r = lane; r < 64; r += 32) {
        bool valid = r < NTOK;
        const __half* p = base + (size_t)(valid ? r : 0) * QKV_N + 256;
#pragma unroll
        for (int j = 0; j < 4; j++) {
            uint4 kv = valid ? *(const uint4*)(p + 8 * j) : make_uint4(0, 0, 0, 0);
            KH[r * 17 + 4 * j + 0] = kv.x;
            KH[r * 17 + 4 * j + 1] = kv.y;
            KH[r * 17 + 4 * j + 2] = kv.z;
            KH[r * 17 + 4 * j + 3] = kv.w;
        }
    }

    // V transposed: lane = d; pack two tokens' halfs per word
    const __half* vbase = base + 512;
#pragma unroll 4
    for (int tp = 0; tp < 32; tp++) {
        int t0 = 2 * tp, t1 = 2 * tp + 1;
        __half a = (t0 < NTOK) ? vbase[(size_t)t0 * QKV_N + lane] : __half(0.f);
        __half b = (t1 < NTOK) ? vbase[(size_t)t1 * QKV_N + lane] : __half(0.f);
        __half2 h = __halves2half2(a, b);
        VTH[lane * 33 + tp] = *reinterpret_cast<uint32_t*>(&h);
    }
    __syncwarp();

    float o[4][4][4];
#pragma unroll
    for (int a = 0; a < 4; a++)
#pragma unroll
        for (int b = 0; b < 4; b++)
#pragma unroll
            for (int r = 0; r < 4; r++) o[a][b][r] = 0.f;

#pragma unroll
    for (int mt = 0; mt < 4; mt++) {
        const int r0 = mt * 16 + gid;
        const int rc0 = min(r0, NTOK - 1);
        const int rc1 = min(r0 + 8, NTOK - 1);
        const __half* q0 = base + (size_t)rc0 * QKV_N;
        const __half* q1 = base + (size_t)rc1 * QKV_N;

        // Q A-fragments: raw uint32 loads (already scaled in GEMM epilogue)
        uint32_t qh[2][4];
#pragma unroll
        for (int ks = 0; ks < 2; ks++) {
            const int f0 = ks * 16 + 2 * t4;
            qh[ks][0] = *(const uint32_t*)(q0 + f0);
            qh[ks][1] = *(const uint32_t*)(q1 + f0);
            qh[ks][2] = *(const uint32_t*)(q0 + f0 + 8);
            qh[ks][3] = *(const uint32_t*)(q1 + f0 + 8);
        }

        float c[8][4];
#pragma unroll
        for (int nt = 0; nt < 8; nt++) { c[nt][0] = c[nt][1] = c[nt][2] = c[nt][3] = 0.f; }
#pragma unroll
        for (int nt = 0; nt < 8; nt++) {
            int cn = nt * 8 + gid;
#pragma unroll
            for (int ks = 0; ks < 2; ks++) {
                int cp = ks * 8 + t4;
                uint32_t b0 = KH[cn * 17 + cp], b1 = KH[cn * 17 + cp + 4];
                mma16816(c[nt], qh[ks][0], qh[ks][1], qh[ks][2], qh[ks][3], b0, b1);
            }
        }

        // bias + shift mask + padding mask
        const int ih0 = rc0 / WS, iw0 = rc0 % WS;
        const int ih1 = rc1 / WS, iw1 = rc1 % WS;
        int hr, wr, rh, rw;
        hr = hbase + ih0; wr = wbase + iw0;
        rh = (hr < 49) ? 0 : ((hr < 53) ? 1 : 2); rw = (wr < 49) ? 0 : ((wr < 53) ? 1 : 2);
        const int rg0 = rh * 3 + rw;
        hr = hbase + ih1; wr = wbase + iw1;
        rh = (hr < 49) ? 0 : ((hr < 53) ? 1 : 2); rw = (wr < 49) ? 0 : ((wr < 53) ? 1 : 2);
        const int rg1 = rh * 3 + rw;

#pragma unroll
        for (int nt = 0; nt < 8; nt++) {
#pragma unroll
            for (int jc = 0; jc < 2; jc++) {
                int j = nt * 8 + 2 * t4 + jc;
                if (j < NTOK) {
                    int jh = j / WS, jw = j % WS;
                    int jhr = hbase + jh, jwr = wbase + jw;
                    int rjh = (jhr < 49) ? 0 : ((jhr < 53) ? 1 : 2);
                    int rjw = (jwr < 49) ? 0 : ((jwr < 53) ? 1 : 2);
                    int rgj = rjh * 3 + rjw;
                    float b0 = TBL[(ih0 - jh + 6) * 13 + (iw0 - jw + 6)];
                    float b1 = TBL[(ih1 - jh + 6) * 13 + (iw1 - jw + 6)];
                    if (rg0 != rgj) b0 -= 100.f;
                    if (rg1 != rgj) b1 -= 100.f;
                    c[nt][jc] += b0;
                    c[nt][2 + jc] += b1;
                } else {
                    c[nt][jc] = -1e30f;
                    c[nt][2 + jc] = -1e30f;
                }
            }
        }

        // softmax over t4 quad
        float m0 = -1e30f, m1 = -1e30f;
#pragma unroll
        for (int nt = 0; nt < 8; nt++) {
            m0 = fmaxf(m0, fmaxf(c[nt][0], c[nt][1]));
            m1 = fmaxf(m1, fmaxf(c[nt][2], c[nt][3]));
        }
        m0 = fmaxf(m0, __shfl_xor_sync(0xffffffffu, m0, 1));
        m0 = fmaxf(m0, __shfl_xor_sync(0xffffffffu, m0, 2));
        m1 = fmaxf(m1, __shfl_xor_sync(0xffffffffu, m1, 1));
        m1 = fmaxf(m1, __shfl_xor_sync(0xffffffffu, m1, 2));
        float s0 = 0.f, s1 = 0.f;
#pragma unroll
        for (int nt = 0; nt < 8; nt++) {
            c[nt][0] = __expf(c[nt][0] - m0); s0 += c[nt][0];
            c[nt][1] = __expf(c[nt][1] - m0); s0 += c[nt][1];
            c[nt][2] = __expf(c[nt][2] - m1); s1 += c[nt][2];
            c[nt][3] = __expf(c[nt][3] - m1); s1 += c[nt][3];
        }
        s0 += __shfl_xor_sync(0xffffffffu, s0, 1);
        s0 += __shfl_xor_sync(0xffffffffu, s0, 2);
        s1 += __shfl_xor_sync(0xffffffffu, s1, 1);
        s1 += __shfl_xor_sync(0xffffffffu, s1, 2);
        const float inv0 = 1.f / s0, inv1 = 1.f / s1;
#pragma unroll
        for (int nt = 0; nt < 8; nt++) {
            c[nt][0] *= inv0; c[nt][1] *= inv0;
            c[nt][2] *= inv1; c[nt][3] *= inv1;
        }

        // O += P V
#pragma unroll
        for (int kt = 0; kt < 4; kt++) {
            uint32_t ph[4];
            ph[0] = pack_h2(c[2 * kt][0],     c[2 * kt][1]);
            ph[1] = pack_h2(c[2 * kt][2],     c[2 * kt][3]);
            ph[2] = pack_h2(c[2 * kt + 1][0], c[2 * kt + 1][1]);
            ph[3] = pack_h2(c[2 * kt + 1][2], c[2 * kt + 1][3]);
#pragma unroll
            for (int nt = 0; nt < 4; nt++) {
                int dn = nt * 8 + gid;
                uint32_t b0 = VTH[dn * 33 + kt * 8 + t4];
                uint32_t b1 = VTH[dn * 33 + kt * 8 + t4 + 4];
                mma16816(o[mt][nt], ph[0], ph[1], ph[2], ph[3], b0, b1);
            }
        }
    }

    // store O as fp16 (input to proj GEMM)
#pragma unroll
    for (int mt = 0; mt < 4; mt++) {
        int i0 = mt * 16 + gid, i1 = i0 + 8;
#pragma unroll
        for (int nt = 0; nt < 4; nt++) {
            int d = nt * 8 + 2 * t4;
            if (i0 < NTOK) {
                *(uint32_t*)(out + ((size_t)win * NTOK + i0) * CH + head * HD + d) =
                    pack_h2(o[mt][nt][0], o[mt][nt][1]);
            }
            if (i1 < NTOK) {
                *(uint32_t*)(out + ((size_t)win * NTOK + i1) * CH + head * HD + d) =
                    pack_h2(o[mt][nt][2], o[mt][nt][3]);
            }
        }
    }
}

extern "C" void kernel_launch(void* const* d_in, const int* in_sizes, int n_in,
                              void* d_out, int out_size) {
    const float* x      = (const float*)d_in[0];
    const float* qkv_w  = (const float*)d_in[1];
    const float* qkv_b  = (const float*)d_in[2];
    const float* proj_w = (const float*)d_in[3];
    const float* proj_b = (const float*)d_in[4];
    const float* table  = (const float*)d_in[5];
    float* out = (float*)d_out;

    __half* qkv_buf;
    __half* attn_buf;
    cudaGetSymbolAddress((void**)&qkv_buf, g_qkv);
    cudaGetSymbolAddress((void**)&attn_buf, g_attnout);

    cudaFuncSetAttribute(tc_gemm<0>, cudaFuncAttributeMaxDynamicSharedMemorySize, SMEM_GEMM);
    cudaFuncSetAttribute(tc_gemm<1>, cudaFuncAttributeMaxDynamicSharedMemorySize, SMEM_GEMM);

    dim3 g1(QKV_N / 256, M_TOTAL / 128);   // (3, 1568)
    tc_gemm<0><<<g1, 512, SMEM_GEMM>>>(x, qkv_w, qkv_b, qkv_buf);

    attn_mma_kernel<<<BATCH * NWIN * NHEAD, 32>>>(qkv_buf, table, attn_buf);

    dim3 g3(CH / 256, M_TOTAL / 128);      // (1, 1568)
    tc_gemm<1><<<g3, 512, SMEM_GEMM>>>(attn_buf, proj_w, proj_b, out);
}

// round 13
// speedup vs baseline: 1.8800x; 1.0615x over previous
#include <cuda_runtime.h>
#include <cuda_fp16.h>
#include <cstdint>

// Problem constants (B=64, H=W=56, C=256, heads=8, hd=32, ws=7, shift=3)
#define IMG 56
#define CH 256
#define NHEAD 8
#define HD 32
#define WS 7
#define NWIN 64
#define NTOK 49
#define BATCH 64
#define M_TOTAL (BATCH * IMG * IMG)   // 200704
#define QKV_N 768
#define QSCALE 0.17677669529663687f

// Scratch (fp16 end-to-end)
__device__ __half g_xh[(size_t)M_TOTAL * CH];         // gathered x, fp16, window order
__device__ __half g_wq[(size_t)QKV_N * CH];           // qkv weight fp16
__device__ __half g_wp[(size_t)CH * CH];              // proj weight fp16
__device__ __half g_qkv[(size_t)M_TOTAL * QKV_N];     // qkv out (q pre-scaled)
__device__ __half g_attnout[(size_t)M_TOTAL * CH];    // attention out

// ---- index helper ------------------------------------------------------
__device__ __forceinline__ int gather_src_row(int m) {
    int win = m / NTOK, n = m - win * NTOK;
    int b = win >> 6, wl = win & 63;
    int hr = (wl >> 3) * WS + n / WS;
    int wr = (wl & 7) * WS + n % WS;
    int h = hr + 3; if (h >= IMG) h -= IMG;
    int w = wr + 3; if (w >= IMG) w -= IMG;
    return (b * IMG + h) * IMG + w;
}

__device__ __forceinline__ uint32_t pack_h2(float a, float b) {
    __half2 h = __floats2half2_rn(a, b);
    return *reinterpret_cast<uint32_t*>(&h);
}

__device__ __forceinline__ void mma16816(float* c,
    uint32_t a0, uint32_t a1, uint32_t a2, uint32_t a3,
    uint32_t b0, uint32_t b1) {
    asm volatile(
        "mma.sync.aligned.m16n8k16.row.col.f32.f16.f16.f32 "
        "{%0,%1,%2,%3}, {%4,%5,%6,%7}, {%8,%9}, {%0,%1,%2,%3};"
        : "+f"(c[0]), "+f"(c[1]), "+f"(c[2]), "+f"(c[3])
        : "r"(a0), "r"(a1), "r"(a2), "r"(a3), "r"(b0), "r"(b1));
}

__device__ __forceinline__ void cp_async16(uint32_t dst, const void* src) {
    asm volatile("cp.async.cg.shared.global [%0], [%1], 16;" :: "r"(dst), "l"(src));
}
__device__ __forceinline__ void cp_commit() { asm volatile("cp.async.commit_group;"); }
__device__ __forceinline__ void cp_wait0()  { asm volatile("cp.async.wait_group 0;"); }

// ---- prep kernels (one-time fp32 -> fp16) -------------------------------
__global__ void __launch_bounds__(256) prep_x(const float* __restrict__ x) {
    int idx = blockIdx.x * 256 + threadIdx.x;          // one per 4 elems
    int m = idx >> 6;
    int k4 = (idx & 63) * 4;
    float4 v = *(const float4*)(x + (size_t)gather_src_row(m) * CH + k4);
    uint2 r;
    r.x = pack_h2(v.x, v.y);
    r.y = pack_h2(v.z, v.w);
    *(uint2*)(g_xh + (size_t)m * CH + k4) = r;
}

__global__ void __launch_bounds__(256) prep_w(const float* __restrict__ w,
                                              __half* __restrict__ wh) {
    int idx = blockIdx.x * 256 + threadIdx.x;
    float4 v = *(const float4*)(w + (size_t)idx * 4);
    uint2 r;
    r.x = pack_h2(v.x, v.y);
    r.y = pack_h2(v.z, v.w);
    *(uint2*)(wh + (size_t)idx * 4) = r;
}

// ---- HMMA GEMM: 128x256 tile, 512 threads, BK=32, cp.async -------------
// All-fp16 inputs. MODE 0: out g_qkv (fp16, QSCALE folded n<256).
//                  MODE 1: out d_out fp32 scattered.
#define BK 32
#define SA 40
#define A_ELEMS (128 * SA)                 // 5120 halfs
#define B_ELEMS (256 * SA)                 // 10240 halfs
#define A_BYTES (A_ELEMS * 2)
#define STG_ELEMS (A_ELEMS + B_ELEMS)
#define STG_BYTES (STG_ELEMS * 2)          // 30720
#define SMEM_GEMM (2 * STG_BYTES)          // 61440

template <int MODE>
__global__ void __launch_bounds__(512, 1) tc_gemm(
    const __half* __restrict__ Ain, const __half* __restrict__ Win,
    const float* __restrict__ bias, void* __restrict__ outptr)
{
    extern __shared__ __half sm[];
    const int tid = threadIdx.x;
    const int wid = tid >> 5;
    const int lane = tid & 31;
    const int gid = lane >> 2;
    const int t4 = lane & 3;
    const int wm = wid & 3;
    const int wn = wid >> 2;
    const int bm = blockIdx.y * 128;
    const int bn = blockIdx.x * 256;

    const uint32_t smem_base = (uint32_t)__cvta_generic_to_shared(sm);

    // cp.async loaders: A row = tid>>2, 16B chunk; B row = tid>>1, 32B (2x16B)
    const int arow = tid >> 2;
    const int ak = (tid & 3) * 8;
    const int brow = tid >> 1;
    const int bk = (tid & 1) * 16;
    const __half* Ag = Ain + (size_t)(bm + arow) * CH + ak;
    const __half* Bg = Win + (size_t)(bn + brow) * CH + bk;

    const uint32_t sA = (uint32_t)((arow * SA + ak) * 2);
    const uint32_t sB = (uint32_t)(A_BYTES + (brow * SA + bk) * 2);

    auto load_stage = [&](int st, int k0) {
        const uint32_t base = smem_base + st * STG_BYTES;
        cp_async16(base + sA, Ag + k0);
        cp_async16(base + sB, Bg + k0);
        cp_async16(base + sB + 16, Bg + k0 + 8);
        cp_commit();
    };

    float acc[2][8][4];
#pragma unroll
    for (int mt = 0; mt < 2; mt++)
#pragma unroll
        for (int nt = 0; nt < 8; nt++)
#pragma unroll
            for (int r = 0; r < 4; r++) acc[mt][nt][r] = 0.f;

    load_stage(0, 0);
    cp_wait0();
    __syncthreads();

    const int NSTAGE = CH / BK;   // 8
    for (int s = 0; s < NSTAGE; s++) {
        const int p = s & 1;
        if (s + 1 < NSTAGE) load_stage((s + 1) & 1, (s + 1) * BK);

        const __half* Ah = sm + p * STG_ELEMS;
        const __half* Bh = Ah + A_ELEMS;
#pragma unroll
        for (int ksub = 0; ksub < 2; ksub++) {
            const int kk = ksub * 16 + 2 * t4;
            uint32_t ah[2][4];
#pragma unroll
            for (int mt = 0; mt < 2; mt++) {
                int r = wm * 32 + mt * 16 + gid;
                ah[mt][0] = *(const uint32_t*)(Ah + r * SA + kk);
                ah[mt][1] = *(const uint32_t*)(Ah + (r + 8) * SA + kk);
                ah[mt][2] = *(const uint32_t*)(Ah + r * SA + kk + 8);
                ah[mt][3] = *(const uint32_t*)(Ah + (r + 8) * SA + kk + 8);
            }
#pragma unroll
            for (int nt = 0; nt < 8; nt++) {
                int c = wn * 64 + nt * 8 + gid;
                uint32_t b0 = *(const uint32_t*)(Bh + c * SA + kk);
                uint32_t b1 = *(const uint32_t*)(Bh + c * SA + kk + 8);
                mma16816(acc[0][nt], ah[0][0], ah[0][1], ah[0][2], ah[0][3], b0, b1);
                mma16816(acc[1][nt], ah[1][0], ah[1][1], ah[1][2], ah[1][3], b0, b1);
            }
        }
        if (s + 1 < NSTAGE) {
            cp_wait0();
            __syncthreads();
        }
    }

    // epilogue
#pragma unroll
    for (int mt = 0; mt < 2; mt++) {
        int m1 = bm + wm * 32 + mt * 16 + gid;
        int m2 = m1 + 8;
        if (MODE == 0) {
            __half* d1 = (__half*)outptr + (size_t)m1 * QKV_N;
            __half* d2 = (__half*)outptr + (size_t)m2 * QKV_N;
#pragma unroll
            for (int nt = 0; nt < 8; nt++) {
                int n = bn + wn * 64 + nt * 8 + 2 * t4;
                float2 bv2 = *(const float2*)(bias + n);
                float sc = (n < 256) ? QSCALE : 1.0f;   // fold q scaling
                *(uint32_t*)(d1 + n) = pack_h2((acc[mt][nt][0] + bv2.x) * sc,
                                               (acc[mt][nt][1] + bv2.y) * sc);
                *(uint32_t*)(d2 + n) = pack_h2((acc[mt][nt][2] + bv2.x) * sc,
                                               (acc[mt][nt][3] + bv2.y) * sc);
            }
        } else {
            float* d1 = (float*)outptr + (size_t)gather_src_row(m1) * CH;
            float* d2 = (float*)outptr + (size_t)gather_src_row(m2) * CH;
#pragma unroll
            for (int nt = 0; nt < 8; nt++) {
                int n = bn + wn * 64 + nt * 8 + 2 * t4;
                float2 bv2 = *(const float2*)(bias + n);
                float2 r1, r2;
                r1.x = acc[mt][nt][0] + bv2.x; r1.y = acc[mt][nt][1] + bv2.y;
                r2.x = acc[mt][nt][2] + bv2.x; r2.y = acc[mt][nt][3] + bv2.y;
                *(float2*)(d1 + n) = r1;
                *(float2*)(d2 + n) = r2;
            }
        }
    }
}

// ---- HMMA window attention: one warp per (window, head), fp16 I/O ------
__global__ void __launch_bounds__(32) attn_mma_kernel(
    const __half* __restrict__ qkv, const float* __restrict__ table,
    __half* __restrict__ out)
{
    const int blk = blockIdx.x;
    const int win = blk >> 3;
    const int head = blk & 7;
    const int lane = threadIdx.x;
    const int gid = lane >> 2;
    const int t4 = lane & 3;
    const int wl = win & 63;
    const int hbase = (wl >> 3) * WS;
    const int wbase = (wl & 7) * WS;

    __shared__ uint32_t KH[64 * 17];
    __shared__ uint32_t VTH[32 * 33];
    __shared__ float TBL[169];

    for (int t = lane; t < 169; t += 32) TBL[t] = table[t * NHEAD + head];

    const __half* base = qkv + (size_t)win * NTOK * QKV_N + head * HD;

    // K: raw fp16 copy into smem, zero padding rows
    for (int r = lane; r < 64; r += 32) {
        bool valid = r < NTOK;
        const __half* p = base + (size_t)(valid ? r : 0) * QKV_N + 256;
#pragma unroll
        for (int j = 0; j < 4; j++) {
            uint4 kv = valid ? *(const uint4*)(p + 8 * j) : make_uint4(0, 0, 0, 0);
            KH[r * 17 + 4 * j + 0] = kv.x;
            KH[r * 17 + 4 * j + 1] = kv.y;
            KH[r * 17 + 4 * j + 2] = kv.z;
            KH[r * 17 + 4 * j + 3] = kv.w;
        }
    }

    // V transposed: lane = d; pack two tokens' halfs per word
    const __half* vbase = base + 512;
#pragma unroll 4
    for (int tp = 0; tp < 32; tp++) {
        int t0 = 2 * tp, t1 = 2 * tp + 1;
        __half a = (t0 < NTOK) ? vbase[(size_t)t0 * QKV_N + lane] : __half(0.f);
        __half b = (t1 < NTOK) ? vbase[(size_t)t1 * QKV_N + lane] : __half(0.f);
        __half2 h = __halves2half2(a, b);
        VTH[lane * 33 + tp] = *reinterpret_cast<uint32_t*>(&h);
    }
    __syncwarp();

    float o[4][4][4];
#pragma unroll
    for (int a = 0; a < 4; a++)
#pragma unroll
        for (int b = 0; b < 4; b++)
#pragma unroll
            for (int r = 0; r < 4; r++) o[a][b][r] = 0.f;

#pragma unroll
    for (int mt = 0; mt < 4; mt++) {
        const int r0 = mt * 16 + gid;
        const int rc0 = min(r0, NTOK - 1);
        const int rc1 = min(r0 + 8, NTOK - 1);
        const __half* q0 = base + (size_t)rc0 * QKV_N;
        const __half* q1 = base + (size_t)rc1 * QKV_N;

        uint32_t qh[2][4];
#pragma unroll
        for (int ks = 0; ks < 2; ks++) {
            const int f0 = ks * 16 + 2 * t4;
            qh[ks][0] = *(const uint32_t*)(q0 + f0);
            qh[ks][1] = *(const uint32_t*)(q1 + f0);
            qh[ks][2] = *(const uint32_t*)(q0 + f0 + 8);
            qh[ks][3] = *(const uint32_t*)(q1 + f0 + 8);
        }

        float c[8][4];
#pragma unroll
        for (int nt = 0; nt < 8; nt++) { c[nt][0] = c[nt][1] = c[nt][2] = c[nt][3] = 0.f; }
#pragma unroll
        for (int nt = 0; nt < 8; nt++) {
            int cn = nt * 8 + gid;
#pragma unroll
            for (int ks = 0; ks < 2; ks++) {
                int cp = ks * 8 + t4;
                uint32_t b0 = KH[cn * 17 + cp], b1 = KH[cn * 17 + cp + 4];
                mma16816(c[nt], qh[ks][0], qh[ks][1], qh[ks][2], qh[ks][3], b0, b1);
            }
        }

        // bias + shift mask + padding mask
        const int ih0 = rc0 / WS, iw0 = rc0 % WS;
        const int ih1 = rc1 / WS, iw1 = rc1 % WS;
        int hr, wr, rh, rw;
        hr = hbase + ih0; wr = wbase + iw0;
        rh = (hr < 49) ? 0 : ((hr < 53) ? 1 : 2); rw = (wr < 49) ? 0 : ((wr < 53) ? 1 : 2);
        const int rg0 = rh * 3 + rw;
        hr = hbase + ih1; wr = wbase + iw1;
        rh = (hr < 49) ? 0 : ((hr < 53) ? 1 : 2); rw = (wr < 49) ? 0 : ((wr < 53) ? 1 : 2);
        const int rg1 = rh * 3 + rw;

#pragma unroll
        for (int nt = 0; nt < 8; nt++) {
#pragma unroll
            for (int jc = 0; jc < 2; jc++) {
                int j = nt * 8 + 2 * t4 + jc;
                if (j < NTOK) {
                    int jh = j / WS, jw = j % WS;
                    int jhr = hbase + jh, jwr = wbase + jw;
                    int rjh = (jhr < 49) ? 0 : ((jhr < 53) ? 1 : 2);
                    int rjw = (jwr < 49) ? 0 : ((jwr < 53) ? 1 : 2);
                    int rgj = rjh * 3 + rjw;
                    float b0 = TBL[(ih0 - jh + 6) * 13 + (iw0 - jw + 6)];
                    float b1 = TBL[(ih1 - jh + 6) * 13 + (iw1 - jw + 6)];
                    if (rg0 != rgj) b0 -= 100.f;
                    if (rg1 != rgj) b1 -= 100.f;
                    c[nt][jc] += b0;
                    c[nt][2 + jc] += b1;
                } else {
                    c[nt][jc] = -1e30f;
                    c[nt][2 + jc] = -1e30f;
                }
            }
        }

        // softmax over t4 quad
        float m0 = -1e30f, m1 = -1e30f;
#pragma unroll
        for (int nt = 0; nt < 8; nt++) {
            m0 = fmaxf(m0, fmaxf(c[nt][0], c[nt][1]));
            m1 = fmaxf(m1, fmaxf(c[nt][2], c[nt][3]));
        }
        m0 = fmaxf(m0, __shfl_xor_sync(0xffffffffu, m0, 1));
        m0 = fmaxf(m0, __shfl_xor_sync(0xffffffffu, m0, 2));
        m1 = fmaxf(m1, __shfl_xor_sync(0xffffffffu, m1, 1));
        m1 = fmaxf(m1, __shfl_xor_sync(0xffffffffu, m1, 2));
        float s0 = 0.f, s1 = 0.f;
#pragma unroll
        for (int nt = 0; nt < 8; nt++) {
            c[nt][0] = __expf(c[nt][0] - m0); s0 += c[nt][0];
            c[nt][1] = __expf(c[nt][1] - m0); s0 += c[nt][1];
            c[nt][2] = __expf(c[nt][2] - m1); s1 += c[nt][2];
            c[nt][3] = __expf(c[nt][3] - m1); s1 += c[nt][3];
        }
        s0 += __shfl_xor_sync(0xffffffffu, s0, 1);
        s0 += __shfl_xor_sync(0xffffffffu, s0, 2);
        s1 += __shfl_xor_sync(0xffffffffu, s1, 1);
        s1 += __shfl_xor_sync(0xffffffffu, s1, 2);
        const float inv0 = 1.f / s0, inv1 = 1.f / s1;
#pragma unroll
        for (int nt = 0; nt < 8; nt++) {
            c[nt][0] *= inv0; c[nt][1] *= inv0;
            c[nt][2] *= inv1; c[nt][3] *= inv1;
        }

        // O += P V
#pragma unroll
        for (int kt = 0; kt < 4; kt++) {
            uint32_t ph[4];
            ph[0] = pack_h2(c[2 * kt][0],     c[2 * kt][1]);
            ph[1] = pack_h2(c[2 * kt][2],     c[2 * kt][3]);
            ph[2] = pack_h2(c[2 * kt + 1][0], c[2 * kt + 1][1]);
            ph[3] = pack_h2(c[2 * kt + 1][2], c[2 * kt + 1][3]);
#pragma unroll
            for (int nt = 0; nt < 4; nt++) {
                int dn = nt * 8 + gid;
                uint32_t b0 = VTH[dn * 33 + kt * 8 + t4];
                uint32_t b1 = VTH[dn * 33 + kt * 8 + t4 + 4];
                mma16816(o[mt][nt], ph[0], ph[1], ph[2], ph[3], b0, b1);
            }
        }
    }

    // store O as fp16 (input to proj GEMM)
#pragma unroll
    for (int mt = 0; mt < 4; mt++) {
        int i0 = mt * 16 + gid, i1 = i0 + 8;
#pragma unroll
        for (int nt = 0; nt < 4; nt++) {
            int d = nt * 8 + 2 * t4;
            if (i0 < NTOK) {
                *(uint32_t*)(out + ((size_t)win * NTOK + i0) * CH + head * HD + d) =
                    pack_h2(o[mt][nt][0], o[mt][nt][1]);
            }
            if (i1 < NTOK) {
                *(uint32_t*)(out + ((size_t)win * NTOK + i1) * CH + head * HD + d) =
                    pack_h2(o[mt][nt][2], o[mt][nt][3]);
            }
        }
    }
}

extern "C" void kernel_launch(void* const* d_in, const int* in_sizes, int n_in,
                              void* d_out, int out_size) {
    const float* x      = (const float*)d_in[0];
    const float* qkv_w  = (const float*)d_in[1];
    const float* qkv_b  = (const float*)d_in[2];
    const float* proj_w = (const float*)d_in[3];
    const float* proj_b = (const float*)d_in[4];
    const float* table  = (const float*)d_in[5];
    float* out = (float*)d_out;

    __half *xh, *wq, *wp, *qkv_buf, *attn_buf;
    cudaGetSymbolAddress((void**)&xh, g_xh);
    cudaGetSymbolAddress((void**)&wq, g_wq);
    cudaGetSymbolAddress((void**)&wp, g_wp);
    cudaGetSymbolAddress((void**)&qkv_buf, g_qkv);
    cudaGetSymbolAddress((void**)&attn_buf, g_attnout);

    cudaFuncSetAttribute(tc_gemm<0>, cudaFuncAttributeMaxDynamicSharedMemorySize, SMEM_GEMM);
    cudaFuncSetAttribute(tc_gemm<1>, cudaFuncAttributeMaxDynamicSharedMemorySize, SMEM_GEMM);

    prep_x<<<(M_TOTAL * (CH / 4)) / 256, 256>>>(x);
    prep_w<<<(QKV_N * CH / 4) / 256, 256>>>(qkv_w, wq);
    prep_w<<<(CH * CH / 4) / 256, 256>>>(proj_w, wp);

    dim3 g1(QKV_N / 256, M_TOTAL / 128);   // (3, 1568)
    tc_gemm<0><<<g1, 512, SMEM_GEMM>>>(xh, wq, qkv_b, qkv_buf);

    attn_mma_kernel<<<BATCH * NWIN * NHEAD, 32>>>(qkv_buf, table, attn_buf);

    dim3 g3(CH / 256, M_TOTAL / 128);      // (1, 1568)
    tc_gemm<1><<<g3, 512, SMEM_GEMM>>>(attn_buf, wp, proj_b, out);
}

// round 14
// speedup vs baseline: 1.8983x; 1.0097x over previous
#include <cuda_runtime.h>
#include <cuda_fp16.h>
#include <cstdint>

// Problem constants (B=64, H=W=56, C=256, heads=8, hd=32, ws=7, shift=3)
#define IMG 56
#define CH 256
#define NHEAD 8
#define HD 32
#define WS 7
#define NWIN 64
#define NTOK 49
#define BATCH 64
#define M_TOTAL (BATCH * IMG * IMG)   // 200704
#define QKV_N 768
#define QSCALE 0.17677669529663687f

// Scratch (fp16 end-to-end)
__device__ __half g_xh[(size_t)M_TOTAL * CH];
__device__ __half g_wq[(size_t)QKV_N * CH];
__device__ __half g_wp[(size_t)CH * CH];
__device__ __half g_qkv[(size_t)M_TOTAL * QKV_N];
__device__ __half g_attnout[(size_t)M_TOTAL * CH];

// ---- index helper ------------------------------------------------------
__device__ __forceinline__ int gather_src_row(int m) {
    int win = m / NTOK, n = m - win * NTOK;
    int b = win >> 6, wl = win & 63;
    int hr = (wl >> 3) * WS + n / WS;
    int wr = (wl & 7) * WS + n % WS;
    int h = hr + 3; if (h >= IMG) h -= IMG;
    int w = wr + 3; if (w >= IMG) w -= IMG;
    return (b * IMG + h) * IMG + w;
}

__device__ __forceinline__ uint32_t pack_h2(float a, float b) {
    __half2 h = __floats2half2_rn(a, b);
    return *reinterpret_cast<uint32_t*>(&h);
}

__device__ __forceinline__ void mma16816(float* c,
    uint32_t a0, uint32_t a1, uint32_t a2, uint32_t a3,
    uint32_t b0, uint32_t b1) {
    asm volatile(
        "mma.sync.aligned.m16n8k16.row.col.f32.f16.f16.f32 "
        "{%0,%1,%2,%3}, {%4,%5,%6,%7}, {%8,%9}, {%0,%1,%2,%3};"
        : "+f"(c[0]), "+f"(c[1]), "+f"(c[2]), "+f"(c[3])
        : "r"(a0), "r"(a1), "r"(a2), "r"(a3), "r"(b0), "r"(b1));
}

__device__ __forceinline__ void cp_async16(uint32_t dst, const void* src) {
    asm volatile("cp.async.cg.shared.global [%0], [%1], 16;" :: "r"(dst), "l"(src));
}
__device__ __forceinline__ void cp_commit() { asm volatile("cp.async.commit_group;"); }
template <int N>
__device__ __forceinline__ void cp_wait() { asm volatile("cp.async.wait_group %0;" :: "n"(N)); }

// ---- prep kernels (one-time fp32 -> fp16) -------------------------------
__global__ void __launch_bounds__(256) prep_x(const float* __restrict__ x) {
    int idx = blockIdx.x * 256 + threadIdx.x;
    int m = idx >> 6;
    int k4 = (idx & 63) * 4;
    float4 v = *(const float4*)(x + (size_t)gather_src_row(m) * CH + k4);
    uint2 r;
    r.x = pack_h2(v.x, v.y);
    r.y = pack_h2(v.z, v.w);
    *(uint2*)(g_xh + (size_t)m * CH + k4) = r;
}

__global__ void __launch_bounds__(256) prep_w(const float* __restrict__ w,
                                              __half* __restrict__ wh) {
    int idx = blockIdx.x * 256 + threadIdx.x;
    float4 v = *(const float4*)(w + (size_t)idx * 4);
    uint2 r;
    r.x = pack_h2(v.x, v.y);
    r.y = pack_h2(v.z, v.w);
    *(uint2*)(wh + (size_t)idx * 4) = r;
}

// ---- HMMA GEMM: 128x256 tile, 512 threads, BK=32, 4-stage cp.async -----
#define BK 32
#define SA 40
#define A_ELEMS (128 * SA)
#define B_ELEMS (256 * SA)
#define A_BYTES (A_ELEMS * 2)
#define STG_ELEMS (A_ELEMS + B_ELEMS)
#define STG_BYTES (STG_ELEMS * 2)          // 30720
#define NPIPE 4
#define SMEM_GEMM (NPIPE * STG_BYTES)      // 122880

template <int MODE>
__global__ void __launch_bounds__(512, 1) tc_gemm(
    const __half* __restrict__ Ain, const __half* __restrict__ Win,
    const float* __restrict__ bias, void* __restrict__ outptr)
{
    extern __shared__ __half sm[];
    const int tid = threadIdx.x;
    const int wid = tid >> 5;
    const int lane = tid & 31;
    const int gid = lane >> 2;
    const int t4 = lane & 3;
    const int wm = wid & 3;
    const int wn = wid >> 2;
    const int bm = blockIdx.y * 128;
    const int bn = blockIdx.x * 256;

    const uint32_t smem_base = (uint32_t)__cvta_generic_to_shared(sm);

    const int arow = tid >> 2;
    const int ak = (tid & 3) * 8;
    const int brow = tid >> 1;
    const int bk = (tid & 1) * 16;
    const __half* Ag = Ain + (size_t)(bm + arow) * CH + ak;
    const __half* Bg = Win + (size_t)(bn + brow) * CH + bk;

    const uint32_t sA = (uint32_t)((arow * SA + ak) * 2);
    const uint32_t sB = (uint32_t)(A_BYTES + (brow * SA + bk) * 2);

    auto load_stage = [&](int st, int k0) {
        const uint32_t base = smem_base + st * STG_BYTES;
        cp_async16(base + sA, Ag + k0);
        cp_async16(base + sB, Bg + k0);
        cp_async16(base + sB + 16, Bg + k0 + 8);
        cp_commit();
    };

    float acc[2][8][4];
#pragma unroll
    for (int mt = 0; mt < 2; mt++)
#pragma unroll
        for (int nt = 0; nt < 8; nt++)
#pragma unroll
            for (int r = 0; r < 4; r++) acc[mt][nt][r] = 0.f;

    // prologue: 3 stages in flight
    load_stage(0, 0);
    load_stage(1, BK);
    load_stage(2, 2 * BK);

    const int NSTAGE = CH / BK;   // 8
    for (int s = 0; s < NSTAGE; s++) {
        cp_wait<2>();             // oldest (stage s) has landed
        __syncthreads();          // all threads' stage-s data visible; stage s-1 consumed by all
        if (s + 3 < NSTAGE) load_stage((s + 3) & (NPIPE - 1), (s + 3) * BK);

        const __half* Ah = sm + (s & (NPIPE - 1)) * STG_ELEMS;
        const __half* Bh = Ah + A_ELEMS;
#pragma unroll
        for (int ksub = 0; ksub < 2; ksub++) {
            const int kk = ksub * 16 + 2 * t4;
            uint32_t ah[2][4];
#pragma unroll
            for (int mt = 0; mt < 2; mt++) {
                int r = wm * 32 + mt * 16 + gid;
                ah[mt][0] = *(const uint32_t*)(Ah + r * SA + kk);
                ah[mt][1] = *(const uint32_t*)(Ah + (r + 8) * SA + kk);
                ah[mt][2] = *(const uint32_t*)(Ah + r * SA + kk + 8);
                ah[mt][3] = *(const uint32_t*)(Ah + (r + 8) * SA + kk + 8);
            }
#pragma unroll
            for (int nt = 0; nt < 8; nt++) {
                int c = wn * 64 + nt * 8 + gid;
                uint32_t b0 = *(const uint32_t*)(Bh + c * SA + kk);
                uint32_t b1 = *(const uint32_t*)(Bh + c * SA + kk + 8);
                mma16816(acc[0][nt], ah[0][0], ah[0][1], ah[0][2], ah[0][3], b0, b1);
                mma16816(acc[1][nt], ah[1][0], ah[1][1], ah[1][2], ah[1][3], b0, b1);
            }
        }
    }

    // epilogue
#pragma unroll
    for (int mt = 0; mt < 2; mt++) {
        int m1 = bm + wm * 32 + mt * 16 + gid;
        int m2 = m1 + 8;
        if (MODE == 0) {
            __half* d1 = (__half*)outptr + (size_t)m1 * QKV_N;
            __half* d2 = (__half*)outptr + (size_t)m2 * QKV_N;
#pragma unroll
            for (int nt = 0; nt < 8; nt++) {
                int n = bn + wn * 64 + nt * 8 + 2 * t4;
                float2 bv2 = *(const float2*)(bias + n);
                float sc = (n < 256) ? QSCALE : 1.0f;
                *(uint32_t*)(d1 + n) = pack_h2((acc[mt][nt][0] + bv2.x) * sc,
                                               (acc[mt][nt][1] + bv2.y) * sc);
                *(uint32_t*)(d2 + n) = pack_h2((acc[mt][nt][2] + bv2.x) * sc,
                                               (acc[mt][nt][3] + bv2.y) * sc);
            }
        } else {
            float* d1 = (float*)outptr + (size_t)gather_src_row(m1) * CH;
            float* d2 = (float*)outptr + (size_t)gather_src_row(m2) * CH;
#pragma unroll
            for (int nt = 0; nt < 8; nt++) {
                int n = bn + wn * 64 + nt * 8 + 2 * t4;
                float2 bv2 = *(const float2*)(bias + n);
                float2 r1, r2;
                r1.x = acc[mt][nt][0] + bv2.x; r1.y = acc[mt][nt][1] + bv2.y;
                r2.x = acc[mt][nt][2] + bv2.x; r2.y = acc[mt][nt][3] + bv2.y;
                *(float2*)(d1 + n) = r1;
                *(float2*)(d2 + n) = r2;
            }
        }
    }
}

// ---- HMMA window attention: one warp per (window, head), fp16 I/O ------
__global__ void __launch_bounds__(32) attn_mma_kernel(
    const __half* __restrict__ qkv, const float* __restrict__ table,
    __half* __restrict__ out)
{
    const int blk = blockIdx.x;
    const int win = blk >> 3;
    const int head = blk & 7;
    const int lane = threadIdx.x;
    const int gid = lane >> 2;
    const int t4 = lane & 3;
    const int wl = win & 63;
    const int hbase = (wl >> 3) * WS;
    const int wbase = (wl & 7) * WS;

    __shared__ uint32_t KH[64 * 17];
    __shared__ uint32_t VTH[32 * 33];
    __shared__ float TBL[169];

    for (int t = lane; t < 169; t += 32) TBL[t] = table[t * NHEAD + head];

    const __half* base = qkv + (size_t)win * NTOK * QKV_N + head * HD;

    for (int r = lane; r < 64; r += 32) {
        bool valid = r < NTOK;
        const __half* p = base + (size_t)(valid ? r : 0) * QKV_N + 256;
#pragma unroll
        for (int j = 0; j < 4; j++) {
            uint4 kv = valid ? *(const uint4*)(p + 8 * j) : make_uint4(0, 0, 0, 0);
            KH[r * 17 + 4 * j + 0] = kv.x;
            KH[r * 17 + 4 * j + 1] = kv.y;
            KH[r * 17 + 4 * j + 2] = kv.z;
            KH[r * 17 + 4 * j + 3] = kv.w;
        }
    }

    const __half* vbase = base + 512;
#pragma unroll 4
    for (int tp = 0; tp < 32; tp++) {
        int t0 = 2 * tp, t1 = 2 * tp + 1;
        __half a = (t0 < NTOK) ? vbase[(size_t)t0 * QKV_N + lane] : __half(0.f);
        __half b = (t1 < NTOK) ? vbase[(size_t)t1 * QKV_N + lane] : __half(0.f);
        __half2 h = __halves2half2(a, b);
        VTH[lane * 33 + tp] = *reinterpret_cast<uint32_t*>(&h);
    }
    __syncwarp();

    float o[4][4][4];
#pragma unroll
    for (int a = 0; a < 4; a++)
#pragma unroll
        for (int b = 0; b < 4; b++)
#pragma unroll
            for (int r = 0; r < 4; r++) o[a][b][r] = 0.f;

#pragma unroll
    for (int mt = 0; mt < 4; mt++) {
        const int r0 = mt * 16 + gid;
        const int rc0 = min(r0, NTOK - 1);
        const int rc1 = min(r0 + 8, NTOK - 1);
        const __half* q0 = base + (size_t)rc0 * QKV_N;
        const __half* q1 = base + (size_t)rc1 * QKV_N;

        uint32_t qh[2][4];
#pragma unroll
        for (int ks = 0; ks < 2; ks++) {
            const int f0 = ks * 16 + 2 * t4;
            qh[ks][0] = *(const uint32_t*)(q0 + f0);
            qh[ks][1] = *(const uint32_t*)(q1 + f0);
            qh[ks][2] = *(const uint32_t*)(q0 + f0 + 8);
            qh[ks][3] = *(const uint32_t*)(q1 + f0 + 8);
        }

        float c[8][4];
#pragma unroll
        for (int nt = 0; nt < 8; nt++) { c[nt][0] = c[nt][1] = c[nt][2] = c[nt][3] = 0.f; }
#pragma unroll
        for (int nt = 0; nt < 8; nt++) {
            int cn = nt * 8 + gid;
#pragma unroll
            for (int ks = 0; ks < 2; ks++) {
                int cp = ks * 8 + t4;
                uint32_t b0 = KH[cn * 17 + cp], b1 = KH[cn * 17 + cp + 4];
                mma16816(c[nt], qh[ks][0], qh[ks][1], qh[ks][2], qh[ks][3], b0, b1);
            }
        }

        const int ih0 = rc0 / WS, iw0 = rc0 % WS;
        const int ih1 = rc1 / WS, iw1 = rc1 % WS;
        int hr, wr, rh, rw;
        hr = hbase + ih0; wr = wbase + iw0;
        rh = (hr < 49) ? 0 : ((hr < 53) ? 1 : 2); rw = (wr < 49) ? 0 : ((wr < 53) ? 1 : 2);
        const int rg0 = rh * 3 + rw;
        hr = hbase + ih1; wr = wbase + iw1;
        rh = (hr < 49) ? 0 : ((hr < 53) ? 1 : 2); rw = (wr < 49) ? 0 : ((wr < 53) ? 1 : 2);
        const int rg1 = rh * 3 + rw;

#pragma unroll
        for (int nt = 0; nt < 8; nt++) {
#pragma unroll
            for (int jc = 0; jc < 2; jc++) {
                int j = nt * 8 + 2 * t4 + jc;
                if (j < NTOK) {
                    int jh = j / WS, jw = j % WS;
                    int jhr = hbase + jh, jwr = wbase + jw;
                    int rjh = (jhr < 49) ? 0 : ((jhr < 53) ? 1 : 2);
                    int rjw = (jwr < 49) ? 0 : ((jwr < 53) ? 1 : 2);
                    int rgj = rjh * 3 + rjw;
                    float b0 = TBL[(ih0 - jh + 6) * 13 + (iw0 - jw + 6)];
                    float b1 = TBL[(ih1 - jh + 6) * 13 + (iw1 - jw + 6)];
                    if (rg0 != rgj) b0 -= 100.f;
                    if (rg1 != rgj) b1 -= 100.f;
                    c[nt][jc] += b0;
                    c[nt][2 + jc] += b1;
                } else {
                    c[nt][jc] = -1e30f;
                    c[nt][2 + jc] = -1e30f;
                }
            }
        }

        float m0 = -1e30f, m1 = -1e30f;
#pragma unroll
        for (int nt = 0; nt < 8; nt++) {
            m0 = fmaxf(m0, fmaxf(c[nt][0], c[nt][1]));
            m1 = fmaxf(m1, fmaxf(c[nt][2], c[nt][3]));
        }
        m0 = fmaxf(m0, __shfl_xor_sync(0xffffffffu, m0, 1));
        m0 = fmaxf(m0, __shfl_xor_sync(0xffffffffu, m0, 2));
        m1 = fmaxf(m1, __shfl_xor_sync(0xffffffffu, m1, 1));
        m1 = fmaxf(m1, __shfl_xor_sync(0xffffffffu, m1, 2));
        float s0 = 0.f, s1 = 0.f;
#pragma unroll
        for (int nt = 0; nt < 8; nt++) {
            c[nt][0] = __expf(c[nt][0] - m0); s0 += c[nt][0];
            c[nt][1] = __expf(c[nt][1] - m0); s0 += c[nt][1];
            c[nt][2] = __expf(c[nt][2] - m1); s1 += c[nt][2];
            c[nt][3] = __expf(c[nt][3] - m1); s1 += c[nt][3];
        }
        s0 += __shfl_xor_sync(0xffffffffu, s0, 1);
        s0 += __shfl_xor_sync(0xffffffffu, s0, 2);
        s1 += __shfl_xor_sync(0xffffffffu, s1, 1);
        s1 += __shfl_xor_sync(0xffffffffu, s1, 2);
        const float inv0 = 1.f / s0, inv1 = 1.f / s1;
#pragma unroll
        for (int nt = 0; nt < 8; nt++) {
            c[nt][0] *= inv0; c[nt][1] *= inv0;
            c[nt][2] *= inv1; c[nt][3] *= inv1;
        }

#pragma unroll
        for (int kt = 0; kt < 4; kt++) {
            uint32_t ph[4];
            ph[0] = pack_h2(c[2 * kt][0],     c[2 * kt][1]);
            ph[1] = pack_h2(c[2 * kt][2],     c[2 * kt][3]);
            ph[2] = pack_h2(c[2 * kt + 1][0], c[2 * kt + 1][1]);
            ph[3] = pack_h2(c[2 * kt + 1][2], c[2 * kt + 1][3]);
#pragma unroll
            for (int nt = 0; nt < 4; nt++) {
                int dn = nt * 8 + gid;
                uint32_t b0 = VTH[dn * 33 + kt * 8 + t4];
                uint32_t b1 = VTH[dn * 33 + kt * 8 + t4 + 4];
                mma16816(o[mt][nt], ph[0], ph[1], ph[2], ph[3], b0, b1);
            }
        }
    }

#pragma unroll
    for (int mt = 0; mt < 4; mt++) {
        int i0 = mt * 16 + gid, i1 = i0 + 8;
#pragma unroll
        for (int nt = 0; nt < 4; nt++) {
            int d = nt * 8 + 2 * t4;
            if (i0 < NTOK) {
                *(uint32_t*)(out + ((size_t)win * NTOK + i0) * CH + head * HD + d) =
                    pack_h2(o[mt][nt][0], o[mt][nt][1]);
            }
            if (i1 < NTOK) {
                *(uint32_t*)(out + ((size_t)win * NTOK + i1) * CH + head * HD + d) =
                    pack_h2(o[mt][nt][2], o[mt][nt][3]);
            }
        }
    }
}

extern "C" void kernel_launch(void* const* d_in, const int* in_sizes, int n_in,
                              void* d_out, int out_size) {
    const float* x      = (const float*)d_in[0];
    const float* qkv_w  = (const float*)d_in[1];
    const float* qkv_b  = (const float*)d_in[2];
    const float* proj_w = (const float*)d_in[3];
    const float* proj_b = (const float*)d_in[4];
    const float* table  = (const float*)d_in[5];
    float* out = (float*)d_out;

    __half *xh, *wq, *wp, *qkv_buf, *attn_buf;
    cudaGetSymbolAddress((void**)&xh, g_xh);
    cudaGetSymbolAddress((void**)&wq, g_wq);
    cudaGetSymbolAddress((void**)&wp, g_wp);
    cudaGetSymbolAddress((void**)&qkv_buf, g_qkv);
    cudaGetSymbolAddress((void**)&attn_buf, g_attnout);

    cudaFuncSetAttribute(tc_gemm<0>, cudaFuncAttributeMaxDynamicSharedMemorySize, SMEM_GEMM);
    cudaFuncSetAttribute(tc_gemm<1>, cudaFuncAttributeMaxDynamicSharedMemorySize, SMEM_GEMM);

    prep_x<<<(M_TOTAL * (CH / 4)) / 256, 256>>>(x);
    prep_w<<<(QKV_N * CH / 4) / 256, 256>>>(qkv_w, wq);
    prep_w<<<(CH * CH / 4) / 256, 256>>>(proj_w, wp);

    dim3 g1(QKV_N / 256, M_TOTAL / 128);   // (3, 1568)
    tc_gemm<0><<<g1, 512, SMEM_GEMM>>>(xh, wq, qkv_b, qkv_buf);

    attn_mma_kernel<<<BATCH * NWIN * NHEAD, 32>>>(qkv_buf, table, attn_buf);

    dim3 g3(CH / 256, M_TOTAL / 128);      // (1, 1568)
    tc_gemm<1><<<g3, 512, SMEM_GEMM>>>(attn_buf, wp, proj_b, out);
}

// round 15
// speedup vs baseline: 1.9714x; 1.0385x over previous
#include <cuda_runtime.h>
#include <cuda_fp16.h>
#include <cstdint>

// Problem constants (B=64, H=W=56, C=256, heads=8, hd=32, ws=7, shift=3)
#define IMG 56
#define CH 256
#define NHEAD 8
#define HD 32
#define WS 7
#define NWIN 64
#define NTOK 49
#define BATCH 64
#define M_TOTAL (BATCH * IMG * IMG)   // 200704
#define QKV_N 768
#define QSCALE 0.17677669529663687f

// Scratch (fp16 end-to-end)
__device__ __half g_xh[(size_t)M_TOTAL * CH];
__device__ __half g_wq[(size_t)QKV_N * CH];
__device__ __half g_wp[(size_t)CH * CH];
__device__ __half g_qkv[(size_t)M_TOTAL * QKV_N];
__device__ __half g_attnout[(size_t)M_TOTAL * CH];

// ---- index helper ------------------------------------------------------
__device__ __forceinline__ int gather_src_row(int m) {
    int win = m / NTOK, n = m - win * NTOK;
    int b = win >> 6, wl = win & 63;
    int hr = (wl >> 3) * WS + n / WS;
    int wr = (wl & 7) * WS + n % WS;
    int h = hr + 3; if (h >= IMG) h -= IMG;
    int w = wr + 3; if (w >= IMG) w -= IMG;
    return (b * IMG + h) * IMG + w;
}

__device__ __forceinline__ uint32_t pack_h2(float a, float b) {
    __half2 h = __floats2half2_rn(a, b);
    return *reinterpret_cast<uint32_t*>(&h);
}

__device__ __forceinline__ void mma16816(float* c,
    uint32_t a0, uint32_t a1, uint32_t a2, uint32_t a3,
    uint32_t b0, uint32_t b1) {
    asm volatile(
        "mma.sync.aligned.m16n8k16.row.col.f32.f16.f16.f32 "
        "{%0,%1,%2,%3}, {%4,%5,%6,%7}, {%8,%9}, {%0,%1,%2,%3};"
        : "+f"(c[0]), "+f"(c[1]), "+f"(c[2]), "+f"(c[3])
        : "r"(a0), "r"(a1), "r"(a2), "r"(a3), "r"(b0), "r"(b1));
}

__device__ __forceinline__ void cp_async16(uint32_t dst, const void* src) {
    asm volatile("cp.async.cg.shared.global [%0], [%1], 16;" :: "r"(dst), "l"(src));
}
__device__ __forceinline__ void cp_commit() { asm volatile("cp.async.commit_group;"); }
template <int N>
__device__ __forceinline__ void cp_wait() { asm volatile("cp.async.wait_group %0;" :: "n"(N)); }

// ---- prep kernels (one-time fp32 -> fp16) -------------------------------
__global__ void __launch_bounds__(256) prep_x(const float* __restrict__ x) {
    int idx = blockIdx.x * 256 + threadIdx.x;
    int m = idx >> 6;
    int k4 = (idx & 63) * 4;
    float4 v = *(const float4*)(x + (size_t)gather_src_row(m) * CH + k4);
    uint2 r;
    r.x = pack_h2(v.x, v.y);
    r.y = pack_h2(v.z, v.w);
    *(uint2*)(g_xh + (size_t)m * CH + k4) = r;
}

__global__ void __launch_bounds__(256) prep_w(const float* __restrict__ w,
                                              __half* __restrict__ wh) {
    int idx = blockIdx.x * 256 + threadIdx.x;
    float4 v = *(const float4*)(w + (size_t)idx * 4);
    uint2 r;
    r.x = pack_h2(v.x, v.y);
    r.y = pack_h2(v.z, v.w);
    *(uint2*)(wh + (size_t)idx * 4) = r;
}

// ---- HMMA GEMM: 128x128 tile, 256 threads, 2 CTAs/SM, 4-stage cp.async -
#define BK 32
#define SA 40
#define A_ELEMS (128 * SA)                 // 5120 halfs
#define B_ELEMS (128 * SA)                 // 5120 halfs
#define A_BYTES (A_ELEMS * 2)              // 10240
#define STG_ELEMS (A_ELEMS + B_ELEMS)      // 10240
#define STG_BYTES (STG_ELEMS * 2)          // 20480
#define NPIPE 4
#define SMEM_GEMM (NPIPE * STG_BYTES)      // 81920 per CTA; 2 CTAs = 163840/SM

template <int MODE>
__global__ void __launch_bounds__(256, 2) tc_gemm(
    const __half* __restrict__ Ain, const __half* __restrict__ Win,
    const float* __restrict__ bias, void* __restrict__ outptr)
{
    extern __shared__ __half sm[];
    const int tid = threadIdx.x;
    const int wid = tid >> 5;
    const int lane = tid & 31;
    const int gid = lane >> 2;
    const int t4 = lane & 3;
    const int wm = wid & 3;          // 4 row groups of 32
    const int wn = wid >> 2;         // 2 col groups of 64
    const int bm = blockIdx.y * 128;
    const int bn = blockIdx.x * 128;

    const uint32_t smem_base = (uint32_t)__cvta_generic_to_shared(sm);

    // loaders: row = tid>>1 (0..127), k half = (tid&1)*16 -> 32B = 2 cp each
    const int lrow = tid >> 1;
    const int lk = (tid & 1) * 16;
    const __half* Ag = Ain + (size_t)(bm + lrow) * CH + lk;
    const __half* Bg = Win + (size_t)(bn + lrow) * CH + lk;

    const uint32_t sA = (uint32_t)((lrow * SA + lk) * 2);
    const uint32_t sB = (uint32_t)(A_BYTES + (lrow * SA + lk) * 2);

    auto load_stage = [&](int st, int k0) {
        const uint32_t base = smem_base + st * STG_BYTES;
        cp_async16(base + sA, Ag + k0);
        cp_async16(base + sA + 16, Ag + k0 + 8);
        cp_async16(base + sB, Bg + k0);
        cp_async16(base + sB + 16, Bg + k0 + 8);
        cp_commit();
    };

    float acc[2][8][4];
#pragma unroll
    for (int mt = 0; mt < 2; mt++)
#pragma unroll
        for (int nt = 0; nt < 8; nt++)
#pragma unroll
            for (int r = 0; r < 4; r++) acc[mt][nt][r] = 0.f;

    // prologue: 3 stages in flight
    load_stage(0, 0);
    load_stage(1, BK);
    load_stage(2, 2 * BK);

    const int NSTAGE = CH / BK;   // 8
    for (int s = 0; s < NSTAGE; s++) {
        cp_wait<2>();
        __syncthreads();
        if (s + 3 < NSTAGE) load_stage((s + 3) & (NPIPE - 1), (s + 3) * BK);

        const __half* Ah = sm + (s & (NPIPE - 1)) * STG_ELEMS;
        const __half* Bh = Ah + A_ELEMS;
#pragma unroll
        for (int ksub = 0; ksub < 2; ksub++) {
            const int kk = ksub * 16 + 2 * t4;
            uint32_t ah[2][4];
#pragma unroll
            for (int mt = 0; mt < 2; mt++) {
                int r = wm * 32 + mt * 16 + gid;
                ah[mt][0] = *(const uint32_t*)(Ah + r * SA + kk);
                ah[mt][1] = *(const uint32_t*)(Ah + (r + 8) * SA + kk);
                ah[mt][2] = *(const uint32_t*)(Ah + r * SA + kk + 8);
                ah[mt][3] = *(const uint32_t*)(Ah + (r + 8) * SA + kk + 8);
            }
#pragma unroll
            for (int nt = 0; nt < 8; nt++) {
                int c = wn * 64 + nt * 8 + gid;
                uint32_t b0 = *(const uint32_t*)(Bh + c * SA + kk);
                uint32_t b1 = *(const uint32_t*)(Bh + c * SA + kk + 8);
                mma16816(acc[0][nt], ah[0][0], ah[0][1], ah[0][2], ah[0][3], b0, b1);
                mma16816(acc[1][nt], ah[1][0], ah[1][1], ah[1][2], ah[1][3], b0, b1);
            }
        }
    }

    // epilogue
#pragma unroll
    for (int mt = 0; mt < 2; mt++) {
        int m1 = bm + wm * 32 + mt * 16 + gid;
        int m2 = m1 + 8;
        if (MODE == 0) {
            __half* d1 = (__half*)outptr + (size_t)m1 * QKV_N;
            __half* d2 = (__half*)outptr + (size_t)m2 * QKV_N;
#pragma unroll
            for (int nt = 0; nt < 8; nt++) {
                int n = bn + wn * 64 + nt * 8 + 2 * t4;
                float2 bv2 = *(const float2*)(bias + n);
                float sc = (n < 256) ? QSCALE : 1.0f;
                *(uint32_t*)(d1 + n) = pack_h2((acc[mt][nt][0] + bv2.x) * sc,
                                               (acc[mt][nt][1] + bv2.y) * sc);
                *(uint32_t*)(d2 + n) = pack_h2((acc[mt][nt][2] + bv2.x) * sc,
                                               (acc[mt][nt][3] + bv2.y) * sc);
            }
        } else {
            float* d1 = (float*)outptr + (size_t)gather_src_row(m1) * CH;
            float* d2 = (float*)outptr + (size_t)gather_src_row(m2) * CH;
#pragma unroll
            for (int nt = 0; nt < 8; nt++) {
                int n = bn + wn * 64 + nt * 8 + 2 * t4;
                float2 bv2 = *(const float2*)(bias + n);
                float2 r1, r2;
                r1.x = acc[mt][nt][0] + bv2.x; r1.y = acc[mt][nt][1] + bv2.y;
                r2.x = acc[mt][nt][2] + bv2.x; r2.y = acc[mt][nt][3] + bv2.y;
                *(float2*)(d1 + n) = r1;
                *(float2*)(d2 + n) = r2;
            }
        }
    }
}

// ---- HMMA window attention: one warp per (window, head), fp16 I/O ------
__global__ void __launch_bounds__(32) attn_mma_kernel(
    const __half* __restrict__ qkv, const float* __restrict__ table,
    __half* __restrict__ out)
{
    const int blk = blockIdx.x;
    const int win = blk >> 3;
    const int head = blk & 7;
    const int lane = threadIdx.x;
    const int gid = lane >> 2;
    const int t4 = lane & 3;
    const int wl = win & 63;
    const int hbase = (wl >> 3) * WS;
    const int wbase = (wl & 7) * WS;

    __shared__ uint32_t KH[64 * 17];
    __shared__ uint32_t VTH[32 * 33];
    __shared__ float TBL[169];

    for (int t = lane; t < 169; t += 32) TBL[t] = table[t * NHEAD + head];

    const __half* base = qkv + (size_t)win * NTOK * QKV_N + head * HD;

    for (int r = lane; r < 64; r += 32) {
        bool valid = r < NTOK;
        const __half* p = base + (size_t)(valid ? r : 0) * QKV_N + 256;
#pragma unroll
        for (int j = 0; j < 4; j++) {
            uint4 kv = valid ? *(const uint4*)(p + 8 * j) : make_uint4(0, 0, 0, 0);
            KH[r * 17 + 4 * j + 0] = kv.x;
            KH[r * 17 + 4 * j + 1] = kv.y;
            KH[r * 17 + 4 * j + 2] = kv.z;
            KH[r * 17 + 4 * j + 3] = kv.w;
        }
    }

    const __half* vbase = base + 512;
#pragma unroll 4
    for (int tp = 0; tp < 32; tp++) {
        int t0 = 2 * tp, t1 = 2 * tp + 1;
        __half a = (t0 < NTOK) ? vbase[(size_t)t0 * QKV_N + lane] : __half(0.f);
        __half b = (t1 < NTOK) ? vbase[(size_t)t1 * QKV_N + lane] : __half(0.f);
        __half2 h = __halves2half2(a, b);
        VTH[lane * 33 + tp] = *reinterpret_cast<uint32_t*>(&h);
    }
    __syncwarp();

    float o[4][4][4];
#pragma unroll
    for (int a = 0; a < 4; a++)
#pragma unroll
        for (int b = 0; b < 4; b++)
#pragma unroll
            for (int r = 0; r < 4; r++) o[a][b][r] = 0.f;

#pragma unroll
    for (int mt = 0; mt < 4; mt++) {
        const int r0 = mt * 16 + gid;
        const int rc0 = min(r0, NTOK - 1);
        const int rc1 = min(r0 + 8, NTOK - 1);
        const __half* q0 = base + (size_t)rc0 * QKV_N;
        const __half* q1 = base + (size_t)rc1 * QKV_N;

        uint32_t qh[2][4];
#pragma unroll
        for (int ks = 0; ks < 2; ks++) {
            const int f0 = ks * 16 + 2 * t4;
            qh[ks][0] = *(const uint32_t*)(q0 + f0);
            qh[ks][1] = *(const uint32_t*)(q1 + f0);
            qh[ks][2] = *(const uint32_t*)(q0 + f0 + 8);
            qh[ks][3] = *(const uint32_t*)(q1 + f0 + 8);
        }

        float c[8][4];
#pragma unroll
        for (int nt = 0; nt < 8; nt++) { c[nt][0] = c[nt][1] = c[nt][2] = c[nt][3] = 0.f; }
#pragma unroll
        for (int nt = 0; nt < 8; nt++) {
            int cn = nt * 8 + gid;
#pragma unroll
            for (int ks = 0; ks < 2; ks++) {
                int cp = ks * 8 + t4;
                uint32_t b0 = KH[cn * 17 + cp], b1 = KH[cn * 17 + cp + 4];
                mma16816(c[nt], qh[ks][0], qh[ks][1], qh[ks][2], qh[ks][3], b0, b1);
            }
        }

        const int ih0 = rc0 / WS, iw0 = rc0 % WS;
        const int ih1 = rc1 / WS, iw1 = rc1 % WS;
        int hr, wr, rh, rw;
        hr = hbase + ih0; wr = wbase + iw0;
        rh = (hr < 49) ? 0 : ((hr < 53) ? 1 : 2); rw = (wr < 49) ? 0 : ((wr < 53) ? 1 : 2);
        const int rg0 = rh * 3 + rw;
        hr = hbase + ih1; wr = wbase + iw1;
        rh = (hr < 49) ? 0 : ((hr < 53) ? 1 : 2); rw = (wr < 49) ? 0 : ((wr < 53) ? 1 : 2);
        const int rg1 = rh * 3 + rw;

#pragma unroll
        for (int nt = 0; nt < 8; nt++) {
#pragma unroll
            for (int jc = 0; jc < 2; jc++) {
                int j = nt * 8 + 2 * t4 + jc;
                if (j < NTOK) {
                    int jh = j / WS, jw = j % WS;
                    int jhr = hbase + jh, jwr = wbase + jw;
                    int rjh = (jhr < 49) ? 0 : ((jhr < 53) ? 1 : 2);
                    int rjw = (jwr < 49) ? 0 : ((jwr < 53) ? 1 : 2);
                    int rgj = rjh * 3 + rjw;
                    float b0 = TBL[(ih0 - jh + 6) * 13 + (iw0 - jw + 6)];
                    float b1 = TBL[(ih1 - jh + 6) * 13 + (iw1 - jw + 6)];
                    if (rg0 != rgj) b0 -= 100.f;
                    if (rg1 != rgj) b1 -= 100.f;
                    c[nt][jc] += b0;
                    c[nt][2 + jc] += b1;
                } else {
                    c[nt][jc] = -1e30f;
                    c[nt][2 + jc] = -1e30f;
                }
            }
        }

        float m0 = -1e30f, m1 = -1e30f;
#pragma unroll
        for (int nt = 0; nt < 8; nt++) {
            m0 = fmaxf(m0, fmaxf(c[nt][0], c[nt][1]));
            m1 = fmaxf(m1, fmaxf(c[nt][2], c[nt][3]));
        }
        m0 = fmaxf(m0, __shfl_xor_sync(0xffffffffu, m0, 1));
        m0 = fmaxf(m0, __shfl_xor_sync(0xffffffffu, m0, 2));
        m1 = fmaxf(m1, __shfl_xor_sync(0xffffffffu, m1, 1));
        m1 = fmaxf(m1, __shfl_xor_sync(0xffffffffu, m1, 2));
        float s0 = 0.f, s1 = 0.f;
#pragma unroll
        for (int nt = 0; nt < 8; nt++) {
            c[nt][0] = __expf(c[nt][0] - m0); s0 += c[nt][0];
            c[nt][1] = __expf(c[nt][1] - m0); s0 += c[nt][1];
            c[nt][2] = __expf(c[nt][2] - m1); s1 += c[nt][2];
            c[nt][3] = __expf(c[nt][3] - m1); s1 += c[nt][3];
        }
        s0 += __shfl_xor_sync(0xffffffffu, s0, 1);
        s0 += __shfl_xor_sync(0xffffffffu, s0, 2);
        s1 += __shfl_xor_sync(0xffffffffu, s1, 1);
        s1 += __shfl_xor_sync(0xffffffffu, s1, 2);
        const float inv0 = 1.f / s0, inv1 = 1.f / s1;
#pragma unroll
        for (int nt = 0; nt < 8; nt++) {
            c[nt][0] *= inv0; c[nt][1] *= inv0;
            c[nt][2] *= inv1; c[nt][3] *= inv1;
        }

#pragma unroll
        for (int kt = 0; kt < 4; kt++) {
            uint32_t ph[4];
            ph[0] = pack_h2(c[2 * kt][0],     c[2 * kt][1]);
            ph[1] = pack_h2(c[2 * kt][2],     c[2 * kt][3]);
            ph[2] = pack_h2(c[2 * kt + 1][0], c[2 * kt + 1][1]);
            ph[3] = pack_h2(c[2 * kt + 1][2], c[2 * kt + 1][3]);
#pragma unroll
            for (int nt = 0; nt < 4; nt++) {
                int dn = nt * 8 + gid;
                uint32_t b0 = VTH[dn * 33 + kt * 8 + t4];
                uint32_t b1 = VTH[dn * 33 + kt * 8 + t4 + 4];
                mma16816(o[mt][nt], ph[0], ph[1], ph[2], ph[3], b0, b1);
            }
        }
    }

#pragma unroll
    for (int mt = 0; mt < 4; mt++) {
        int i0 = mt * 16 + gid, i1 = i0 + 8;
#pragma unroll
        for (int nt = 0; nt < 4; nt++) {
            int d = nt * 8 + 2 * t4;
            if (i0 < NTOK) {
                *(uint32_t*)(out + ((size_t)win * NTOK + i0) * CH + head * HD + d) =
                    pack_h2(o[mt][nt][0], o[mt][nt][1]);
            }
            if (i1 < NTOK) {
                *(uint32_t*)(out + ((size_t)win * NTOK + i1) * CH + head * HD + d) =
                    pack_h2(o[mt][nt][2], o[mt][nt][3]);
            }
        }
    }
}

extern "C" void kernel_launch(void* const* d_in, const int* in_sizes, int n_in,
                              void* d_out, int out_size) {
    const float* x      = (const float*)d_in[0];
    const float* qkv_w  = (const float*)d_in[1];
    const float* qkv_b  = (const float*)d_in[2];
    const float* proj_w = (const float*)d_in[3];
    const float* proj_b = (const float*)d_in[4];
    const float* table  = (const float*)d_in[5];
    float* out = (float*)d_out;

    __half *xh, *wq, *wp, *qkv_buf, *attn_buf;
    cudaGetSymbolAddress((void**)&xh, g_xh);
    cudaGetSymbolAddress((void**)&wq, g_wq);
    cudaGetSymbolAddress((void**)&wp, g_wp);
    cudaGetSymbolAddress((void**)&qkv_buf, g_qkv);
    cudaGetSymbolAddress((void**)&attn_buf, g_attnout);

    cudaFuncSetAttribute(tc_gemm<0>, cudaFuncAttributeMaxDynamicSharedMemorySize, SMEM_GEMM);
    cudaFuncSetAttribute(tc_gemm<1>, cudaFuncAttributeMaxDynamicSharedMemorySize, SMEM_GEMM);

    prep_x<<<(M_TOTAL * (CH / 4)) / 256, 256>>>(x);
    prep_w<<<(QKV_N * CH / 4) / 256, 256>>>(qkv_w, wq);
    prep_w<<<(CH * CH / 4) / 256, 256>>>(proj_w, wp);

    dim3 g1(QKV_N / 128, M_TOTAL / 128);   // (6, 1568)
    tc_gemm<0><<<g1, 256, SMEM_GEMM>>>(xh, wq, qkv_b, qkv_buf);

    attn_mma_kernel<<<BATCH * NWIN * NHEAD, 32>>>(qkv_buf, table, attn_buf);

    dim3 g3(CH / 128, M_TOTAL / 128);      // (2, 1568)
    tc_gemm<1><<<g3, 256, SMEM_GEMM>>>(attn_buf, wp, proj_b, out);
}

// round 16
// speedup vs baseline: 1.9871x; 1.0080x over previous
#include <cuda_runtime.h>
#include <cuda_fp16.h>
#include <cstdint>

// Problem constants (B=64, H=W=56, C=256, heads=8, hd=32, ws=7, shift=3)
#define IMG 56
#define CH 256
#define NHEAD 8
#define HD 32
#define WS 7
#define NWIN 64
#define NTOK 49
#define BATCH 64
#define M_TOTAL (BATCH * IMG * IMG)   // 200704
#define QKV_N 768
#define QSCALE 0.17677669529663687f

// Scratch (fp16 end-to-end)
// g_qkv layout: [24][M_TOTAL][32] halfs; chunk c = qtype*8 + head (q pre-scaled)
__device__ __half g_xh[(size_t)M_TOTAL * CH];
__device__ __half g_wq[(size_t)QKV_N * CH];
__device__ __half g_wp[(size_t)CH * CH];
__device__ __half g_qkv[(size_t)M_TOTAL * QKV_N];
__device__ __half g_attnout[(size_t)M_TOTAL * CH];

// ---- index helper ------------------------------------------------------
__device__ __forceinline__ int gather_src_row(int m) {
    int win = m / NTOK, n = m - win * NTOK;
    int b = win >> 6, wl = win & 63;
    int hr = (wl >> 3) * WS + n / WS;
    int wr = (wl & 7) * WS + n % WS;
    int h = hr + 3; if (h >= IMG) h -= IMG;
    int w = wr + 3; if (w >= IMG) w -= IMG;
    return (b * IMG + h) * IMG + w;
}

__device__ __forceinline__ uint32_t pack_h2(float a, float b) {
    __half2 h = __floats2half2_rn(a, b);
    return *reinterpret_cast<uint32_t*>(&h);
}

__device__ __forceinline__ void mma16816(float* c,
    uint32_t a0, uint32_t a1, uint32_t a2, uint32_t a3,
    uint32_t b0, uint32_t b1) {
    asm volatile(
        "mma.sync.aligned.m16n8k16.row.col.f32.f16.f16.f32 "
        "{%0,%1,%2,%3}, {%4,%5,%6,%7}, {%8,%9}, {%0,%1,%2,%3};"
        : "+f"(c[0]), "+f"(c[1]), "+f"(c[2]), "+f"(c[3])
        : "r"(a0), "r"(a1), "r"(a2), "r"(a3), "r"(b0), "r"(b1));
}

__device__ __forceinline__ void cp_async16(uint32_t dst, const void* src) {
    asm volatile("cp.async.cg.shared.global [%0], [%1], 16;" :: "r"(dst), "l"(src));
}
__device__ __forceinline__ void cp_commit() { asm volatile("cp.async.commit_group;"); }
template <int N>
__device__ __forceinline__ void cp_wait() { asm volatile("cp.async.wait_group %0;" :: "n"(N)); }

// ---- prep kernels (one-time fp32 -> fp16) -------------------------------
__global__ void __launch_bounds__(256) prep_x(const float* __restrict__ x) {
    int idx = blockIdx.x * 256 + threadIdx.x;
    int m = idx >> 6;
    int k4 = (idx & 63) * 4;
    float4 v = *(const float4*)(x + (size_t)gather_src_row(m) * CH + k4);
    uint2 r;
    r.x = pack_h2(v.x, v.y);
    r.y = pack_h2(v.z, v.w);
    *(uint2*)(g_xh + (size_t)m * CH + k4) = r;
}

__global__ void __launch_bounds__(256) prep_w(const float* __restrict__ w,
                                              __half* __restrict__ wh) {
    int idx = blockIdx.x * 256 + threadIdx.x;
    float4 v = *(const float4*)(w + (size_t)idx * 4);
    uint2 r;
    r.x = pack_h2(v.x, v.y);
    r.y = pack_h2(v.z, v.w);
    *(uint2*)(wh + (size_t)idx * 4) = r;
}

// ---- HMMA GEMM: 128x128 tile, 256 threads, 2 CTAs/SM, 4-stage cp.async -
#define BK 32
#define SA 40
#define A_ELEMS (128 * SA)
#define B_ELEMS (128 * SA)
#define A_BYTES (A_ELEMS * 2)
#define STG_ELEMS (A_ELEMS + B_ELEMS)
#define STG_BYTES (STG_ELEMS * 2)          // 20480
#define NPIPE 4
#define SMEM_GEMM (NPIPE * STG_BYTES)      // 81920 per CTA

template <int MODE>
__global__ void __launch_bounds__(256, 2) tc_gemm(
    const __half* __restrict__ Ain, const __half* __restrict__ Win,
    const float* __restrict__ bias, void* __restrict__ outptr)
{
    extern __shared__ __half sm[];
    const int tid = threadIdx.x;
    const int wid = tid >> 5;
    const int lane = tid & 31;
    const int gid = lane >> 2;
    const int t4 = lane & 3;
    const int wm = wid & 3;
    const int wn = wid >> 2;
    const int bm = blockIdx.y * 128;
    const int bn = blockIdx.x * 128;

    const uint32_t smem_base = (uint32_t)__cvta_generic_to_shared(sm);

    const int lrow = tid >> 1;
    const int lk = (tid & 1) * 16;
    const __half* Ag = Ain + (size_t)(bm + lrow) * CH + lk;
    const __half* Bg = Win + (size_t)(bn + lrow) * CH + lk;

    const uint32_t sA = (uint32_t)((lrow * SA + lk) * 2);
    const uint32_t sB = (uint32_t)(A_BYTES + (lrow * SA + lk) * 2);

    auto load_stage = [&](int st, int k0) {
        const uint32_t base = smem_base + st * STG_BYTES;
        cp_async16(base + sA, Ag + k0);
        cp_async16(base + sA + 16, Ag + k0 + 8);
        cp_async16(base + sB, Bg + k0);
        cp_async16(base + sB + 16, Bg + k0 + 8);
        cp_commit();
    };

    float acc[2][8][4];
#pragma unroll
    for (int mt = 0; mt < 2; mt++)
#pragma unroll
        for (int nt = 0; nt < 8; nt++)
#pragma unroll
            for (int r = 0; r < 4; r++) acc[mt][nt][r] = 0.f;

    load_stage(0, 0);
    load_stage(1, BK);
    load_stage(2, 2 * BK);

    const int NSTAGE = CH / BK;   // 8
    for (int s = 0; s < NSTAGE; s++) {
        cp_wait<2>();
        __syncthreads();
        if (s + 3 < NSTAGE) load_stage((s + 3) & (NPIPE - 1), (s + 3) * BK);

        const __half* Ah = sm + (s & (NPIPE - 1)) * STG_ELEMS;
        const __half* Bh = Ah + A_ELEMS;
#pragma unroll
        for (int ksub = 0; ksub < 2; ksub++) {
            const int kk = ksub * 16 + 2 * t4;
            uint32_t ah[2][4];
#pragma unroll
            for (int mt = 0; mt < 2; mt++) {
                int r = wm * 32 + mt * 16 + gid;
                ah[mt][0] = *(const uint32_t*)(Ah + r * SA + kk);
                ah[mt][1] = *(const uint32_t*)(Ah + (r + 8) * SA + kk);
                ah[mt][2] = *(const uint32_t*)(Ah + r * SA + kk + 8);
                ah[mt][3] = *(const uint32_t*)(Ah + (r + 8) * SA + kk + 8);
            }
#pragma unroll
            for (int nt = 0; nt < 8; nt++) {
                int c = wn * 64 + nt * 8 + gid;
                uint32_t b0 = *(const uint32_t*)(Bh + c * SA + kk);
                uint32_t b1 = *(const uint32_t*)(Bh + c * SA + kk + 8);
                mma16816(acc[0][nt], ah[0][0], ah[0][1], ah[0][2], ah[0][3], b0, b1);
                mma16816(acc[1][nt], ah[1][0], ah[1][1], ah[1][2], ah[1][3], b0, b1);
            }
        }
    }

    // epilogue
#pragma unroll
    for (int mt = 0; mt < 2; mt++) {
        int m1 = bm + wm * 32 + mt * 16 + gid;
        int m2 = m1 + 8;
        if (MODE == 0) {
            // head-major layout: chunk c = n>>5, offset ((c*M + m)*32 + (n&31))
            __half* o = (__half*)outptr;
#pragma unroll
            for (int nt = 0; nt < 8; nt++) {
                int n = bn + wn * 64 + nt * 8 + 2 * t4;
                int cch = n >> 5, d = n & 31;
                float2 bv2 = *(const float2*)(bias + n);
                float sc = (n < 256) ? QSCALE : 1.0f;
                *(uint32_t*)(o + ((size_t)cch * M_TOTAL + m1) * 32 + d) =
                    pack_h2((acc[mt][nt][0] + bv2.x) * sc, (acc[mt][nt][1] + bv2.y) * sc);
                *(uint32_t*)(o + ((size_t)cch * M_TOTAL + m2) * 32 + d) =
                    pack_h2((acc[mt][nt][2] + bv2.x) * sc, (acc[mt][nt][3] + bv2.y) * sc);
            }
        } else {
            float* d1 = (float*)outptr + (size_t)gather_src_row(m1) * CH;
            float* d2 = (float*)outptr + (size_t)gather_src_row(m2) * CH;
#pragma unroll
            for (int nt = 0; nt < 8; nt++) {
                int n = bn + wn * 64 + nt * 8 + 2 * t4;
                float2 bv2 = *(const float2*)(bias + n);
                float2 r1, r2;
                r1.x = acc[mt][nt][0] + bv2.x; r1.y = acc[mt][nt][1] + bv2.y;
                r2.x = acc[mt][nt][2] + bv2.x; r2.y = acc[mt][nt][3] + bv2.y;
                *(float2*)(d1 + n) = r1;
                *(float2*)(d2 + n) = r2;
            }
        }
    }
}

// ---- HMMA window attention: one warp per (window, head), contiguous QKV
__global__ void __launch_bounds__(32) attn_mma_kernel(
    const __half* __restrict__ qkv, const float* __restrict__ table,
    __half* __restrict__ out)
{
    const int blk = blockIdx.x;
    const int win = blk >> 3;
    const int head = blk & 7;
    const int lane = threadIdx.x;
    const int gid = lane >> 2;
    const int t4 = lane & 3;
    const int wl = win & 63;
    const int hbase = (wl >> 3) * WS;
    const int wbase = (wl & 7) * WS;

    __shared__ uint32_t KH[64 * 17];
    __shared__ uint32_t VTH[32 * 33];
    __shared__ float TBL[169];

    for (int t = lane; t < 169; t += 32) TBL[t] = table[t * NHEAD + head];

    // contiguous per-(win,head) tiles: 49 rows x 32 halfs each
    const __half* qbase = qkv + ((size_t)(head)      * M_TOTAL + (size_t)win * NTOK) * HD;
    const __half* kbase = qkv + ((size_t)(8 + head)  * M_TOTAL + (size_t)win * NTOK) * HD;
    const __half* vbase = qkv + ((size_t)(16 + head) * M_TOTAL + (size_t)win * NTOK) * HD;

    // K: contiguous coalesced copy (49*32 halfs = 196 uint4)
    for (int idx = lane; idx < 196; idx += 32) {
        int e = idx * 8;           // half offset
        int r = e >> 5;
        int c2 = (e & 31) >> 1;    // word offset in row (0,4,8,12)
        uint4 kv = *(const uint4*)(kbase + e);
        KH[r * 17 + c2 + 0] = kv.x;
        KH[r * 17 + c2 + 1] = kv.y;
        KH[r * 17 + c2 + 2] = kv.z;
        KH[r * 17 + c2 + 3] = kv.w;
    }
    // zero padding rows 49..63
    for (int w = lane; w < 15 * 16; w += 32) {
        int r = 49 + w / 16;
        KH[r * 17 + (w & 15)] = 0u;
    }

    // V transposed: per token, 32 lanes read 64B contiguous
#pragma unroll 4
    for (int tp = 0; tp < 32; tp++) {
        int t0 = 2 * tp, t1 = 2 * tp + 1;
        __half a = (t0 < NTOK) ? vbase[t0 * HD + lane] : __half(0.f);
        __half b = (t1 < NTOK) ? vbase[t1 * HD + lane] : __half(0.f);
        __half2 h = __halves2half2(a, b);
        VTH[lane * 33 + tp] = *reinterpret_cast<uint32_t*>(&h);
    }
    __syncwarp();

    float o[4][4][4];
#pragma unroll
    for (int a = 0; a < 4; a++)
#pragma unroll
        for (int b = 0; b < 4; b++)
#pragma unroll
            for (int r = 0; r < 4; r++) o[a][b][r] = 0.f;

#pragma unroll
    for (int mt = 0; mt < 4; mt++) {
        const int r0 = mt * 16 + gid;
        const int rc0 = min(r0, NTOK - 1);
        const int rc1 = min(r0 + 8, NTOK - 1);
        const __half* q0 = qbase + rc0 * HD;
        const __half* q1 = qbase + rc1 * HD;

        uint32_t qh[2][4];
#pragma unroll
        for (int ks = 0; ks < 2; ks++) {
            const int f0 = ks * 16 + 2 * t4;
            qh[ks][0] = *(const uint32_t*)(q0 + f0);
            qh[ks][1] = *(const uint32_t*)(q1 + f0);
            qh[ks][2] = *(const uint32_t*)(q0 + f0 + 8);
            qh[ks][3] = *(const uint32_t*)(q1 + f0 + 8);
        }

        float c[8][4];
#pragma unroll
        for (int nt = 0; nt < 8; nt++) { c[nt][0] = c[nt][1] = c[nt][2] = c[nt][3] = 0.f; }
#pragma unroll
        for (int nt = 0; nt < 8; nt++) {
            int cn = nt * 8 + gid;
#pragma unroll
            for (int ks = 0; ks < 2; ks++) {
                int cp = ks * 8 + t4;
                uint32_t b0 = KH[cn * 17 + cp], b1 = KH[cn * 17 + cp + 4];
                mma16816(c[nt], qh[ks][0], qh[ks][1], qh[ks][2], qh[ks][3], b0, b1);
            }
        }

        const int ih0 = rc0 / WS, iw0 = rc0 % WS;
        const int ih1 = rc1 / WS, iw1 = rc1 % WS;
        int hr, wr, rh, rw;
        hr = hbase + ih0; wr = wbase + iw0;
        rh = (hr < 49) ? 0 : ((hr < 53) ? 1 : 2); rw = (wr < 49) ? 0 : ((wr < 53) ? 1 : 2);
        const int rg0 = rh * 3 + rw;
        hr = hbase + ih1; wr = wbase + iw1;
        rh = (hr < 49) ? 0 : ((hr < 53) ? 1 : 2); rw = (wr < 49) ? 0 : ((wr < 53) ? 1 : 2);
        const int rg1 = rh * 3 + rw;

#pragma unroll
        for (int nt = 0; nt < 8; nt++) {
#pragma unroll
            for (int jc = 0; jc < 2; jc++) {
                int j = nt * 8 + 2 * t4 + jc;
                if (j < NTOK) {
                    int jh = j / WS, jw = j % WS;
                    int jhr = hbase + jh, jwr = wbase + jw;
                    int rjh = (jhr < 49) ? 0 : ((jhr < 53) ? 1 : 2);
                    int rjw = (jwr < 49) ? 0 : ((jwr < 53) ? 1 : 2);
                    int rgj = rjh * 3 + rjw;
                    float b0 = TBL[(ih0 - jh + 6) * 13 + (iw0 - jw + 6)];
                    float b1 = TBL[(ih1 - jh + 6) * 13 + (iw1 - jw + 6)];
                    if (rg0 != rgj) b0 -= 100.f;
                    if (rg1 != rgj) b1 -= 100.f;
                    c[nt][jc] += b0;
                    c[nt][2 + jc] += b1;
                } else {
                    c[nt][jc] = -1e30f;
                    c[nt][2 + jc] = -1e30f;
                }
            }
        }

        float m0 = -1e30f, m1 = -1e30f;
#pragma unroll
        for (int nt = 0; nt < 8; nt++) {
            m0 = fmaxf(m0, fmaxf(c[nt][0], c[nt][1]));
            m1 = fmaxf(m1, fmaxf(c[nt][2], c[nt][3]));
        }
        m0 = fmaxf(m0, __shfl_xor_sync(0xffffffffu, m0, 1));
        m0 = fmaxf(m0, __shfl_xor_sync(0xffffffffu, m0, 2));
        m1 = fmaxf(m1, __shfl_xor_sync(0xffffffffu, m1, 1));
        m1 = fmaxf(m1, __shfl_xor_sync(0xffffffffu, m1, 2));
        float s0 = 0.f, s1 = 0.f;
#pragma unroll
        for (int nt = 0; nt < 8; nt++) {
            c[nt][0] = __expf(c[nt][0] - m0); s0 += c[nt][0];
            c[nt][1] = __expf(c[nt][1] - m0); s0 += c[nt][1];
            c[nt][2] = __expf(c[nt][2] - m1); s1 += c[nt][2];
            c[nt][3] = __expf(c[nt][3] - m1); s1 += c[nt][3];
        }
        s0 += __shfl_xor_sync(0xffffffffu, s0, 1);
        s0 += __shfl_xor_sync(0xffffffffu, s0, 2);
        s1 += __shfl_xor_sync(0xffffffffu, s1, 1);
        s1 += __shfl_xor_sync(0xffffffffu, s1, 2);
        const float inv0 = 1.f / s0, inv1 = 1.f / s1;
#pragma unroll
        for (int nt = 0; nt < 8; nt++) {
            c[nt][0] *= inv0; c[nt][1] *= inv0;
            c[nt][2] *= inv1; c[nt][3] *= inv1;
        }

#pragma unroll
        for (int kt = 0; kt < 4; kt++) {
            uint32_t ph[4];
            ph[0] = pack_h2(c[2 * kt][0],     c[2 * kt][1]);
            ph[1] = pack_h2(c[2 * kt][2],     c[2 * kt][3]);
            ph[2] = pack_h2(c[2 * kt + 1][0], c[2 * kt + 1][1]);
            ph[3] = pack_h2(c[2 * kt + 1][2], c[2 * kt + 1][3]);
#pragma unroll
            for (int nt = 0; nt < 4; nt++) {
                int dn = nt * 8 + gid;
                uint32_t b0 = VTH[dn * 33 + kt * 8 + t4];
                uint32_t b1 = VTH[dn * 33 + kt * 8 + t4 + 4];
                mma16816(o[mt][nt], ph[0], ph[1], ph[2], ph[3], b0, b1);
            }
        }
    }

#pragma unroll
    for (int mt = 0; mt < 4; mt++) {
        int i0 = mt * 16 + gid, i1 = i0 + 8;
#pragma unroll
        for (int nt = 0; nt < 4; nt++) {
            int d = nt * 8 + 2 * t4;
            if (i0 < NTOK) {
                *(uint32_t*)(out + ((size_t)win * NTOK + i0) * CH + head * HD + d) =
                    pack_h2(o[mt][nt][0], o[mt][nt][1]);
            }
            if (i1 < NTOK) {
                *(uint32_t*)(out + ((size_t)win * NTOK + i1) * CH + head * HD + d) =
                    pack_h2(o[mt][nt][2], o[mt][nt][3]);
            }
        }
    }
}

extern "C" void kernel_launch(void* const* d_in, const int* in_sizes, int n_in,
                              void* d_out, int out_size) {
    const float* x      = (const float*)d_in[0];
    const float* qkv_w  = (const float*)d_in[1];
    const float* qkv_b  = (const float*)d_in[2];
    const float* proj_w = (const float*)d_in[3];
    const float* proj_b = (const float*)d_in[4];
    const float* table  = (const float*)d_in[5];
    float* out = (float*)d_out;

    __half *xh, *wq, *wp, *qkv_buf, *attn_buf;
    cudaGetSymbolAddress((void**)&xh, g_xh);
    cudaGetSymbolAddress((void**)&wq, g_wq);
    cudaGetSymbolAddress((void**)&wp, g_wp);
    cudaGetSymbolAddress((void**)&qkv_buf, g_qkv);
    cudaGetSymbolAddress((void**)&attn_buf, g_attnout);

    cudaFuncSetAttribute(tc_gemm<0>, cudaFuncAttributeMaxDynamicSharedMemorySize, SMEM_GEMM);
    cudaFuncSetAttribute(tc_gemm<1>, cudaFuncAttributeMaxDynamicSharedMemorySize, SMEM_GEMM);

    prep_x<<<(M_TOTAL * (CH / 4)) / 256, 256>>>(x);
    prep_w<<<(QKV_N * CH / 4) / 256, 256>>>(qkv_w, wq);
    prep_w<<<(CH * CH / 4) / 256, 256>>>(proj_w, wp);

    dim3 g1(QKV_N / 128, M_TOTAL / 128);   // (6, 1568)
    tc_gemm<0><<<g1, 256, SMEM_GEMM>>>(xh, wq, qkv_b, qkv_buf);

    attn_mma_kernel<<<BATCH * NWIN * NHEAD, 32>>>(qkv_buf, table, attn_buf);

    dim3 g3(CH / 128, M_TOTAL / 128);      // (2, 1568)
    tc_gemm<1><<<g3, 256, SMEM_GEMM>>>(attn_buf, wp, proj_b, out);
}